// round 8
// baseline (speedup 1.0000x reference)
#include <cuda_runtime.h>
#include <cuda_bf16.h>
#include <math.h>
#include <stdint.h>

#define BDIM   4
#define TXQ    4096
#define TXFK   256
#define DMODEL 1024
#define DTEXT  768
#define NHEADS 16
#define HDIM   64
#define MQ     (BDIM*TXQ)     // 16384
#define MKV    (BDIM*TXFK)    // 1024
#define DFF    4096
#define ATT_SCALE 0.125f

// ---------------- scratch (device globals) -----------------------------------
__device__ float g_q   [(size_t)MQ  * DMODEL];
__device__ float g_k   [(size_t)MKV * DMODEL];
__device__ float g_v   [(size_t)MKV * DMODEL];
__device__ float g_res [(size_t)MQ  * DMODEL];

// split-bf16: activations [hi | lo | hi], weights (transposed) [hi | hi | lo]
__device__ __nv_bfloat16 g_xs   [(size_t)MQ  * 3 * DMODEL];
__device__ __nv_bfloat16 g_xfs  [(size_t)MKV * 3 * DTEXT];
__device__ __nv_bfloat16 g_attns[(size_t)MQ  * 3 * DMODEL];
__device__ __nv_bfloat16 g_lns  [(size_t)MQ  * 3 * DMODEL];
__device__ __nv_bfloat16 g_hs   [(size_t)MQ  * 3 * DFF];
__device__ __nv_bfloat16 g_wq   [(size_t)DMODEL * 3 * DMODEL];
__device__ __nv_bfloat16 g_wk   [(size_t)DMODEL * 3 * DTEXT];
__device__ __nv_bfloat16 g_wv   [(size_t)DMODEL * 3 * DTEXT];
__device__ __nv_bfloat16 g_wo   [(size_t)DMODEL * 3 * DMODEL];
__device__ __nv_bfloat16 g_w1   [(size_t)DFF    * 3 * DMODEL];
__device__ __nv_bfloat16 g_w2   [(size_t)DMODEL * 3 * DFF];

__device__ __forceinline__ float gelu_exact(float v) {
    return 0.5f * v * (1.0f + erff(v * 0.7071067811865476f));
}

// ---------------- PTX helpers (target-portable, sm_80+) -----------------------
__device__ __forceinline__ uint32_t smem_u32(const void* p) {
    uint32_t a;
    asm("{ .reg .u64 t; cvta.to.shared.u64 t, %1; cvt.u32.u64 %0, t; }"
        : "=r"(a) : "l"(p));
    return a;
}
__device__ __forceinline__ void cp16(uint32_t s, const void* g) {
    asm volatile("cp.async.cg.shared.global [%0], [%1], 16;" :: "r"(s), "l"(g));
}
__device__ __forceinline__ void ldsm4(uint32_t* r, uint32_t a) {
    asm volatile("ldmatrix.sync.aligned.m8n8.x4.shared.b16 {%0,%1,%2,%3}, [%4];"
        : "=r"(r[0]), "=r"(r[1]), "=r"(r[2]), "=r"(r[3]) : "r"(a));
}
__device__ __forceinline__ void mma16816(float* c, const uint32_t* a,
                                         uint32_t b0, uint32_t b1) {
    asm volatile(
        "mma.sync.aligned.m16n8k16.row.col.f32.bf16.bf16.f32 "
        "{%0,%1,%2,%3}, {%4,%5,%6,%7}, {%8,%9}, {%0,%1,%2,%3};"
        : "+f"(c[0]), "+f"(c[1]), "+f"(c[2]), "+f"(c[3])
        : "r"(a[0]), "r"(a[1]), "r"(a[2]), "r"(a[3]), "r"(b0), "r"(b1));
}
__device__ __forceinline__ uint32_t pack_bf2(float a, float b) {
    __nv_bfloat162 t = __floats2bfloat162_rn(a, b);
    uint32_t u; memcpy(&u, &t, 4); return u;
}

// ---------------- bf16x3 HMMA GEMM --------------------------------------------
// C[M,N] = A'[M,Kp] @ B'[N,Kp]^T (Kp = 3*K_orig), BM=256, BN=128, BK=64.
// 512 threads = 16 warps, 4(M)x4(N) grid, warp tile 64x32.
// 3-stage cp.async pipeline, one barrier/iter. L2-friendly CTA swizzle.
// MODE 0: Cf = acc + bias
// MODE 2: split(gelu(acc + bias)) -> Cb [hi|lo|hi], row width 3*KOUT
// MODE 3: Cf = acc + bias + res1 + res2
#define STAGE_BYTES 49152       // 32KB A + 16KB B
#define NSTAGE 3
#define RASTER_G 16

template<int MODE>
__global__ void __launch_bounds__(512, 1) mma_gemm(
    int Nn, int Kp,
    const __nv_bfloat16* __restrict__ A, const __nv_bfloat16* __restrict__ Bw,
    const float* __restrict__ bias,
    const float* __restrict__ res1, const float* __restrict__ res2,
    float* __restrict__ Cf, __nv_bfloat16* __restrict__ Cb, int KOUT)
{
    extern __shared__ char smraw[];
    const uint32_t smb = smem_u32(smraw);

    const int tid = threadIdx.x;
    // ---- L2-aware rasterization: strips of RASTER_G M-rows, col-major inside
    const int numX = gridDim.x, numY = gridDim.y;
    const int bid = blockIdx.y * numX + blockIdx.x;
    const int strip = RASTER_G * numX;
    const int sIdx = bid / strip;
    const int rIdx = bid % strip;
    const int gRows = (numY - sIdx * RASTER_G) < RASTER_G ? (numY - sIdx * RASTER_G)
                                                          : RASTER_G;
    const int by = sIdx * RASTER_G + (rIdx % gRows);
    const int bx = rIdx / gRows;

    const int w = tid >> 5, lane = tid & 31;
    const int m0w = (w & 3) * 64;        // 4 M-blocks of 64 rows
    const int n0w = (w >> 2) * 32;       // 4 N-blocks of 32 cols

    const __nv_bfloat16* Abase = A  + (size_t)(by * 256) * Kp;
    const __nv_bfloat16* Bbase = Bw + (size_t)(bx * 128) * Kp;
    const int nch = Kp >> 6;

    auto load_stage = [&](int c, int s) {
        const uint32_t sa = smb + s * STAGE_BYTES;
        const uint32_t sb = sa + 32768;
        const int k0 = c * 64;
#pragma unroll
        for (int i = 0; i < 4; i++) {    // A: 256 rows x 8 x 16B = 2048 chunks
            int idx = tid + i * 512;
            int row = idx >> 3, cc = idx & 7;
            uint32_t off = row * 128 + ((cc ^ (row & 7)) << 4);
            cp16(sa + off, Abase + (size_t)row * Kp + k0 + cc * 8);
        }
#pragma unroll
        for (int i = 0; i < 2; i++) {    // B: 128 rows x 8 x 16B = 1024 chunks
            int idx = tid + i * 512;
            int row = idx >> 3, cc = idx & 7;
            uint32_t off = row * 128 + ((cc ^ (row & 7)) << 4);
            cp16(sb + off, Bbase + (size_t)row * Kp + k0 + cc * 8);
        }
        asm volatile("cp.async.commit_group;" ::: "memory");
    };

    float acc[4][4][4];
#pragma unroll
    for (int i = 0; i < 4; i++)
#pragma unroll
        for (int j = 0; j < 4; j++)
#pragma unroll
            for (int q = 0; q < 4; q++) acc[i][j][q] = 0.0f;

    const int a_row = m0w + (lane & 15);
    const int a_ccb = lane >> 4;
    const int b_row = n0w + (lane & 7) + ((lane >> 4) << 3);
    const int b_ccb = (lane >> 3) & 1;

    load_stage(0, 0);
    if (nch > 1) load_stage(1, 1);

    for (int c = 0; c < nch; c++) {
        const int s = c % NSTAGE;
        if (c + 1 < nch) asm volatile("cp.async.wait_group 1;" ::: "memory");
        else             asm volatile("cp.async.wait_group 0;" ::: "memory");
        __syncthreads();
        if (c + 2 < nch) load_stage(c + 2, (c + 2) % NSTAGE);

        const uint32_t sa = smb + s * STAGE_BYTES;
        const uint32_t sb = sa + 32768;
#pragma unroll
        for (int kk = 0; kk < 4; kk++) {
            uint32_t af[4][4];
#pragma unroll
            for (int mi = 0; mi < 4; mi++) {
                int row = a_row + mi * 16;
                int cc = kk * 2 + a_ccb;
                ldsm4(af[mi], sa + row * 128 + ((cc ^ (row & 7)) << 4));
            }
#pragma unroll
            for (int nj = 0; nj < 2; nj++) {
                uint32_t bf[4];
                int row = b_row + nj * 16;
                int cc = kk * 2 + b_ccb;
                ldsm4(bf, sb + row * 128 + ((cc ^ (row & 7)) << 4));
#pragma unroll
                for (int mi = 0; mi < 4; mi++) {
                    mma16816(acc[mi][nj * 2],     af[mi], bf[0], bf[1]);
                    mma16816(acc[mi][nj * 2 + 1], af[mi], bf[2], bf[3]);
                }
            }
        }
    }

    // ---- epilogue from register accumulators
    const int g = lane >> 2, t = lane & 3;
#pragma unroll
    for (int mi = 0; mi < 4; mi++) {
#pragma unroll
        for (int ni = 0; ni < 4; ni++) {
            const int col = bx * 128 + n0w + ni * 8 + 2 * t;
            const float b0 = __ldg(bias + col);
            const float b1 = __ldg(bias + col + 1);
            const int row0 = by * 256 + m0w + mi * 16 + g;
#pragma unroll
            for (int h = 0; h < 2; h++) {
                const int row = row0 + h * 8;
                float v0 = acc[mi][ni][2 * h]     + b0;
                float v1 = acc[mi][ni][2 * h + 1] + b1;
                if (MODE == 2) {
                    v0 = gelu_exact(v0); v1 = gelu_exact(v1);
                    __nv_bfloat16 h0 = __float2bfloat16(v0);
                    __nv_bfloat16 h1 = __float2bfloat16(v1);
                    __nv_bfloat16 l0 = __float2bfloat16(v0 - __bfloat162float(h0));
                    __nv_bfloat16 l1 = __float2bfloat16(v1 - __bfloat162float(h1));
                    uint32_t hp = pack_bf2(__bfloat162float(h0), __bfloat162float(h1));
                    uint32_t lp = pack_bf2(__bfloat162float(l0), __bfloat162float(l1));
                    const size_t rb = (size_t)row * (3 * KOUT) + col;
                    *(uint32_t*)(Cb + rb)            = hp;
                    *(uint32_t*)(Cb + rb + KOUT)     = lp;
                    *(uint32_t*)(Cb + rb + 2 * KOUT) = hp;
                } else {
                    const size_t base = (size_t)row * Nn + col;
                    if (MODE == 3) {
                        v0 += res1[base]     + res2[base];
                        v1 += res1[base + 1] + res2[base + 1];
                    }
                    *(float2*)(Cf + base) = make_float2(v0, v1);
                }
            }
        }
    }
}

// ---------------- split conversions -------------------------------------------
__global__ void asplit_kernel(const float* __restrict__ X, __nv_bfloat16* __restrict__ Y,
                              int M, int K)
{
    size_t i = (size_t)blockIdx.x * blockDim.x + threadIdx.x;
    if (i >= (size_t)M * K) return;
    int m = (int)(i / K), k = (int)(i % K);
    float v = X[i];
    __nv_bfloat16 hi = __float2bfloat16(v);
    __nv_bfloat16 lo = __float2bfloat16(v - __bfloat162float(hi));
    size_t rb = (size_t)m * 3 * K;
    Y[rb + k] = hi; Y[rb + K + k] = lo; Y[rb + 2 * K + k] = hi;
}

__global__ void wsplit_kernel(const float* __restrict__ W, __nv_bfloat16* __restrict__ Y,
                              int K, int N)
{
    size_t i = (size_t)blockIdx.x * blockDim.x + threadIdx.x;
    if (i >= (size_t)K * N) return;
    int n = (int)(i / K), k = (int)(i % K);
    float v = W[(size_t)k * N + n];
    __nv_bfloat16 hi = __float2bfloat16(v);
    __nv_bfloat16 lo = __float2bfloat16(v - __bfloat162float(hi));
    size_t rb = (size_t)n * 3 * K;
    Y[rb + k] = hi; Y[rb + K + k] = hi; Y[rb + 2 * K + k] = lo;
}

// ---------------- attention: 4 q/warp-iter, fused bf16x3 split output ----------
#define QPB 256
#define KPAD 65

__global__ void __launch_bounds__(256) attn_kernel(
    const float* __restrict__ Q, const float* __restrict__ K,
    const float* __restrict__ V, __nv_bfloat16* __restrict__ O)
{
    extern __shared__ float sm[];
    float* Ks = sm;                      // 256*65
    float* Vs = Ks + 256 * KPAD;         // 256*65
    float* qs = Vs + 256 * KPAD;         // 8 warps * 4 q * 64
    float* ps = qs + 8 * 4 * 64;         // 8 warps * 4 q * 256

    const int nchunk = TXQ / QPB;
    const int bid   = blockIdx.x;
    const int chunk = bid % nchunk;
    const int h     = (bid / nchunk) % NHEADS;
    const int b     = bid / (nchunk * NHEADS);

    const int tid  = threadIdx.x;
    const int lane = tid & 31;
    const int w    = tid >> 5;

    for (int i = tid; i < 256 * 16; i += 256) {
        int j  = i >> 4;
        int dq = (i & 15) * 4;
        size_t gbase = (size_t)(b * TXFK + j) * DMODEL + h * HDIM + dq;
        float4 kv = *(const float4*)(K + gbase);
        float4 vv = *(const float4*)(V + gbase);
        Ks[j * KPAD + dq + 0] = kv.x; Ks[j * KPAD + dq + 1] = kv.y;
        Ks[j * KPAD + dq + 2] = kv.z; Ks[j * KPAD + dq + 3] = kv.w;
        Vs[j * KPAD + dq + 0] = vv.x; Vs[j * KPAD + dq + 1] = vv.y;
        Vs[j * KPAD + dq + 2] = vv.z; Vs[j * KPAD + dq + 3] = vv.w;
    }
    __syncthreads();

    float* qw = qs + w * 4 * 64;
    float* pw = ps + w * 4 * 256;

    for (int qt = 0; qt < 8; qt++) {
        const size_t qrow0 = (size_t)b * TXQ + (size_t)chunk * QPB + w * 32 + qt * 4;
#pragma unroll
        for (int r = 0; r < 4; r++) {
            const float* qp = Q + (qrow0 + r) * DMODEL + h * HDIM;
            qw[r * 64 + lane]      = qp[lane];
            qw[r * 64 + lane + 32] = qp[lane + 32];
        }
        __syncwarp();

        float s[4][8];
#pragma unroll
        for (int r = 0; r < 4; r++)
#pragma unroll
            for (int c = 0; c < 8; c++) s[r][c] = 0.0f;

        for (int d = 0; d < 64; d++) {
            float kv[8];
#pragma unroll
            for (int c = 0; c < 8; c++) kv[c] = Ks[(lane + 32 * c) * KPAD + d];
            float qd[4];
#pragma unroll
            for (int r = 0; r < 4; r++) qd[r] = qw[r * 64 + d];
#pragma unroll
            for (int r = 0; r < 4; r++)
#pragma unroll
                for (int c = 0; c < 8; c++) s[r][c] += qd[r] * kv[c];
        }

#pragma unroll
        for (int r = 0; r < 4; r++) {
#pragma unroll
            for (int c = 0; c < 8; c++) s[r][c] *= ATT_SCALE;
            float mx = s[r][0];
#pragma unroll
            for (int c = 1; c < 8; c++) mx = fmaxf(mx, s[r][c]);
#pragma unroll
            for (int o = 16; o; o >>= 1) mx = fmaxf(mx, __shfl_xor_sync(~0u, mx, o));
            float sum = 0.0f;
#pragma unroll
            for (int c = 0; c < 8; c++) { s[r][c] = __expf(s[r][c] - mx); sum += s[r][c]; }
#pragma unroll
            for (int o = 16; o; o >>= 1) sum += __shfl_xor_sync(~0u, sum, o);
            float inv = 1.0f / sum;
#pragma unroll
            for (int c = 0; c < 8; c++) pw[r * 256 + lane + 32 * c] = s[r][c] * inv;
        }
        __syncwarp();

        float o0[4], o1[4];
#pragma unroll
        for (int r = 0; r < 4; r++) { o0[r] = 0.0f; o1[r] = 0.0f; }
        for (int j = 0; j < 256; j += 2) {
            float va0 = Vs[j * KPAD + lane];
            float va1 = Vs[j * KPAD + lane + 32];
            float vb0 = Vs[(j + 1) * KPAD + lane];
            float vb1 = Vs[(j + 1) * KPAD + lane + 32];
#pragma unroll
            for (int r = 0; r < 4; r++) {
                float pa = pw[r * 256 + j];
                float pb = pw[r * 256 + j + 1];
                o0[r] += pa * va0 + pb * vb0;
                o1[r] += pa * va1 + pb * vb1;
            }
        }
        // fused [hi|lo|hi] split write (row width 3*DMODEL)
#pragma unroll
        for (int r = 0; r < 4; r++) {
            const size_t rb = (qrow0 + r) * (size_t)(3 * DMODEL) + h * HDIM;
            __nv_bfloat16 h0 = __float2bfloat16(o0[r]);
            __nv_bfloat16 l0 = __float2bfloat16(o0[r] - __bfloat162float(h0));
            __nv_bfloat16 h1 = __float2bfloat16(o1[r]);
            __nv_bfloat16 l1 = __float2bfloat16(o1[r] - __bfloat162float(h1));
            O[rb + lane]                   = h0;
            O[rb + DMODEL + lane]          = l0;
            O[rb + 2 * DMODEL + lane]      = h0;
            O[rb + lane + 32]              = h1;
            O[rb + DMODEL + lane + 32]     = l1;
            O[rb + 2 * DMODEL + lane + 32] = h1;
        }
        __syncwarp();
    }
}

// ---------------- LayerNorm -> split bf16 --------------------------------------
__global__ void __launch_bounds__(256) ln_split_kernel(
    const float* __restrict__ X, const float* __restrict__ gw,
    const float* __restrict__ bw, __nv_bfloat16* __restrict__ Y)
{
    const int row = blockIdx.x;
    const int t = threadIdx.x;
    float4 v = ((const float4*)(X + (size_t)row * DMODEL))[t];
    float s1 = v.x + v.y + v.z + v.w;
    float s2 = v.x * v.x + v.y * v.y + v.z * v.z + v.w * v.w;
#pragma unroll
    for (int o = 16; o; o >>= 1) {
        s1 += __shfl_xor_sync(~0u, s1, o);
        s2 += __shfl_xor_sync(~0u, s2, o);
    }
    __shared__ float r1[8], r2[8];
    const int w = t >> 5, lane = t & 31;
    if (lane == 0) { r1[w] = s1; r2[w] = s2; }
    __syncthreads();
    if (w == 0) {
        s1 = (lane < 8) ? r1[lane] : 0.0f;
        s2 = (lane < 8) ? r2[lane] : 0.0f;
#pragma unroll
        for (int o = 4; o; o >>= 1) {
            s1 += __shfl_xor_sync(~0u, s1, o);
            s2 += __shfl_xor_sync(~0u, s2, o);
        }
        if (lane == 0) { r1[0] = s1; r2[0] = s2; }
    }
    __syncthreads();
    const float mean = r1[0] * (1.0f / DMODEL);
    const float var  = r2[0] * (1.0f / DMODEL) - mean * mean;
    const float rstd = rsqrtf(var + 1e-5f);
    float4 g4 = ((const float4*)gw)[t];
    float4 b4 = ((const float4*)bw)[t];
    float vv[4];
    vv[0] = (v.x - mean) * rstd * g4.x + b4.x;
    vv[1] = (v.y - mean) * rstd * g4.y + b4.y;
    vv[2] = (v.z - mean) * rstd * g4.z + b4.z;
    vv[3] = (v.w - mean) * rstd * g4.w + b4.w;

    const size_t rb = (size_t)row * 3 * DMODEL;
    const int c = t * 4;
    uint32_t hp[2], lp[2];
#pragma unroll
    for (int jj = 0; jj < 2; jj++) {
        __nv_bfloat16 h0 = __float2bfloat16(vv[2*jj]);
        __nv_bfloat16 h1 = __float2bfloat16(vv[2*jj+1]);
        __nv_bfloat16 l0 = __float2bfloat16(vv[2*jj]   - __bfloat162float(h0));
        __nv_bfloat16 l1 = __float2bfloat16(vv[2*jj+1] - __bfloat162float(h1));
        hp[jj] = pack_bf2(__bfloat162float(h0), __bfloat162float(h1));
        lp[jj] = pack_bf2(__bfloat162float(l0), __bfloat162float(l1));
    }
    *(uint2*)(Y + rb + c)              = make_uint2(hp[0], hp[1]);
    *(uint2*)(Y + rb + DMODEL + c)     = make_uint2(lp[0], lp[1]);
    *(uint2*)(Y + rb + 2 * DMODEL + c) = make_uint2(hp[0], hp[1]);
}

// ---------------- launch -------------------------------------------------------
extern "C" void kernel_launch(void* const* d_in, const int* in_sizes, int n_in,
                              void* d_out, int out_size)
{
    const float* x    = (const float*)d_in[0];
    const float* xf   = (const float*)d_in[1];
    const float* Wq   = (const float*)d_in[2];
    const float* bq   = (const float*)d_in[3];
    const float* Wk   = (const float*)d_in[4];
    const float* bk   = (const float*)d_in[5];
    const float* Wv   = (const float*)d_in[6];
    const float* bv   = (const float*)d_in[7];
    const float* Wo   = (const float*)d_in[8];
    const float* bo   = (const float*)d_in[9];
    const float* ln_g = (const float*)d_in[10];
    const float* ln_b = (const float*)d_in[11];
    const float* W1   = (const float*)d_in[12];
    const float* b1   = (const float*)d_in[13];
    const float* W2   = (const float*)d_in[14];
    const float* b2   = (const float*)d_in[15];
    float* out = (float*)d_out;

    float *q, *k, *v, *res;
    __nv_bfloat16 *xs, *xfs, *attns, *lns, *hs, *wq, *wk, *wv, *wo, *w1, *w2;
    cudaGetSymbolAddress((void**)&q,     g_q);
    cudaGetSymbolAddress((void**)&k,     g_k);
    cudaGetSymbolAddress((void**)&v,     g_v);
    cudaGetSymbolAddress((void**)&res,   g_res);
    cudaGetSymbolAddress((void**)&xs,    g_xs);
    cudaGetSymbolAddress((void**)&xfs,   g_xfs);
    cudaGetSymbolAddress((void**)&attns, g_attns);
    cudaGetSymbolAddress((void**)&lns,   g_lns);
    cudaGetSymbolAddress((void**)&hs,    g_hs);
    cudaGetSymbolAddress((void**)&wq,    g_wq);
    cudaGetSymbolAddress((void**)&wk,    g_wk);
    cudaGetSymbolAddress((void**)&wv,    g_wv);
    cudaGetSymbolAddress((void**)&wo,    g_wo);
    cudaGetSymbolAddress((void**)&w1,    g_w1);
    cudaGetSymbolAddress((void**)&w2,    g_w2);

    const int GEMM_SMEM = NSTAGE * STAGE_BYTES;   // 144KB
    cudaFuncSetAttribute(mma_gemm<0>, cudaFuncAttributeMaxDynamicSharedMemorySize, GEMM_SMEM);
    cudaFuncSetAttribute(mma_gemm<2>, cudaFuncAttributeMaxDynamicSharedMemorySize, GEMM_SMEM);
    cudaFuncSetAttribute(mma_gemm<3>, cudaFuncAttributeMaxDynamicSharedMemorySize, GEMM_SMEM);
    const size_t attn_smem =
        (size_t)(2 * 256 * KPAD + 8 * 4 * 64 + 8 * 4 * 256) * sizeof(float);
    cudaFuncSetAttribute(attn_kernel, cudaFuncAttributeMaxDynamicSharedMemorySize,
                         (int)attn_smem);

    dim3 blk(256);
    dim3 gblk(512);
    auto cdiv = [](size_t a, size_t b) { return (unsigned)((a + b - 1) / b); };

    // weight transposition + splits
    wsplit_kernel<<<cdiv((size_t)DMODEL * DMODEL, 256), blk>>>(Wq, wq, DMODEL, DMODEL);
    wsplit_kernel<<<cdiv((size_t)DTEXT  * DMODEL, 256), blk>>>(Wk, wk, DTEXT,  DMODEL);
    wsplit_kernel<<<cdiv((size_t)DTEXT  * DMODEL, 256), blk>>>(Wv, wv, DTEXT,  DMODEL);
    wsplit_kernel<<<cdiv((size_t)DMODEL * DMODEL, 256), blk>>>(Wo, wo, DMODEL, DMODEL);
    wsplit_kernel<<<cdiv((size_t)DMODEL * DFF,    256), blk>>>(W1, w1, DMODEL, DFF);
    wsplit_kernel<<<cdiv((size_t)DFF    * DMODEL, 256), blk>>>(W2, w2, DFF,    DMODEL);
    // activation splits
    asplit_kernel<<<cdiv((size_t)MQ  * DMODEL, 256), blk>>>(x,  xs,  MQ,  DMODEL);
    asplit_kernel<<<cdiv((size_t)MKV * DTEXT,  256), blk>>>(xf, xfs, MKV, DTEXT);

    // Q = x@Wq + bq ; K/V = xf@W{k,v} + b
    mma_gemm<0><<<dim3(DMODEL / 128, MQ / 256), gblk, GEMM_SMEM>>>(
        DMODEL, 3 * DMODEL, xs, wq, bq, nullptr, nullptr, q, nullptr, 0);
    mma_gemm<0><<<dim3(DMODEL / 128, MKV / 256), gblk, GEMM_SMEM>>>(
        DMODEL, 3 * DTEXT, xfs, wk, bk, nullptr, nullptr, k, nullptr, 0);
    mma_gemm<0><<<dim3(DMODEL / 128, MKV / 256), gblk, GEMM_SMEM>>>(
        DMODEL, 3 * DTEXT, xfs, wv, bv, nullptr, nullptr, v, nullptr, 0);

    // attention (writes split-bf16 output directly)
    attn_kernel<<<BDIM * NHEADS * (TXQ / QPB), blk, attn_smem>>>(q, k, v, attns);

    // out = attn@Wo + bo (residual base)
    mma_gemm<0><<<dim3(DMODEL / 128, MQ / 256), gblk, GEMM_SMEM>>>(
        DMODEL, 3 * DMODEL, attns, wo, bo, nullptr, nullptr, res, nullptr, 0);

    // LayerNorm -> split
    ln_split_kernel<<<MQ, blk>>>(res, ln_g, ln_b, lns);

    // h = GELU(ln@W1 + b1) -> split directly
    mma_gemm<2><<<dim3(DFF / 128, MQ / 256), gblk, GEMM_SMEM>>>(
        DFF, 3 * DMODEL, lns, w1, b1, nullptr, nullptr, nullptr, hs, DFF);

    // final = h@W2 + b2 + res + x
    mma_gemm<3><<<dim3(DMODEL / 128, MQ / 256), gblk, GEMM_SMEM>>>(
        DMODEL, 3 * DFF, hs, w2, b2, res, x, out, nullptr, 0);
}

// round 9
// speedup vs baseline: 1.1417x; 1.1417x over previous
#include <cuda_runtime.h>
#include <cuda_bf16.h>
#include <math.h>
#include <stdint.h>

#define BDIM   4
#define TXQ    4096
#define TXFK   256
#define DMODEL 1024
#define DTEXT  768
#define NHEADS 16
#define HDIM   64
#define MQ     (BDIM*TXQ)     // 16384
#define MKV    (BDIM*TXFK)    // 1024
#define DFF    4096
#define ATT_SCALE 0.125f

// ---------------- scratch (device globals) -----------------------------------
__device__ float g_q   [(size_t)MQ  * DMODEL];
__device__ float g_k   [(size_t)MKV * DMODEL];
__device__ float g_v   [(size_t)MKV * DMODEL];
__device__ float g_res [(size_t)MQ  * DMODEL];

// split-bf16: activations [hi | lo | hi], weights (transposed) [hi | hi | lo]
__device__ __nv_bfloat16 g_xs   [(size_t)MQ  * 3 * DMODEL];
__device__ __nv_bfloat16 g_xfs  [(size_t)MKV * 3 * DTEXT];
__device__ __nv_bfloat16 g_attns[(size_t)MQ  * 3 * DMODEL];
__device__ __nv_bfloat16 g_lns  [(size_t)MQ  * 3 * DMODEL];
__device__ __nv_bfloat16 g_hs   [(size_t)MQ  * 3 * DFF];
__device__ __nv_bfloat16 g_wq   [(size_t)DMODEL * 3 * DMODEL];
__device__ __nv_bfloat16 g_wk   [(size_t)DMODEL * 3 * DTEXT];
__device__ __nv_bfloat16 g_wv   [(size_t)DMODEL * 3 * DTEXT];
__device__ __nv_bfloat16 g_wo   [(size_t)DMODEL * 3 * DMODEL];
__device__ __nv_bfloat16 g_w1   [(size_t)DFF    * 3 * DMODEL];
__device__ __nv_bfloat16 g_w2   [(size_t)DMODEL * 3 * DFF];

__device__ __forceinline__ float gelu_exact(float v) {
    return 0.5f * v * (1.0f + erff(v * 0.7071067811865476f));
}

// ---------------- PTX helpers (target-portable, sm_80+) -----------------------
__device__ __forceinline__ uint32_t smem_u32(const void* p) {
    uint32_t a;
    asm("{ .reg .u64 t; cvta.to.shared.u64 t, %1; cvt.u32.u64 %0, t; }"
        : "=r"(a) : "l"(p));
    return a;
}
__device__ __forceinline__ void cp16(uint32_t s, const void* g) {
    asm volatile("cp.async.cg.shared.global [%0], [%1], 16;" :: "r"(s), "l"(g));
}
__device__ __forceinline__ void ldsm4(uint32_t* r, uint32_t a) {
    asm volatile("ldmatrix.sync.aligned.m8n8.x4.shared.b16 {%0,%1,%2,%3}, [%4];"
        : "=r"(r[0]), "=r"(r[1]), "=r"(r[2]), "=r"(r[3]) : "r"(a));
}
__device__ __forceinline__ void mma16816(float* c, const uint32_t* a,
                                         uint32_t b0, uint32_t b1) {
    asm volatile(
        "mma.sync.aligned.m16n8k16.row.col.f32.bf16.bf16.f32 "
        "{%0,%1,%2,%3}, {%4,%5,%6,%7}, {%8,%9}, {%0,%1,%2,%3};"
        : "+f"(c[0]), "+f"(c[1]), "+f"(c[2]), "+f"(c[3])
        : "r"(a[0]), "r"(a[1]), "r"(a[2]), "r"(a[3]), "r"(b0), "r"(b1));
}
__device__ __forceinline__ uint32_t pack_bf2(float a, float b) {
    __nv_bfloat162 t = __floats2bfloat162_rn(a, b);
    uint32_t u; memcpy(&u, &t, 4); return u;
}

// ---------------- bf16x3 HMMA GEMM (R7 config) --------------------------------
// C[M,N] = A'[M,Kp] @ B'[N,Kp]^T (Kp = 3*K_orig), BM=BN=128, BK=64.
// 256 threads = 8 warps, 4(M)x2(N) grid, warp tile 32x64.
// 3-stage cp.async pipeline, one barrier/iter. L2-friendly CTA swizzle (G=16).
#define STAGE_BYTES 32768       // 16KB A + 16KB B
#define NSTAGE 3
#define RASTER_G 16

template<int MODE>
__global__ void __launch_bounds__(256, 2) mma_gemm(
    int Nn, int Kp,
    const __nv_bfloat16* __restrict__ A, const __nv_bfloat16* __restrict__ Bw,
    const float* __restrict__ bias,
    const float* __restrict__ res1, const float* __restrict__ res2,
    float* __restrict__ Cf, __nv_bfloat16* __restrict__ Cb, int KOUT)
{
    extern __shared__ char smraw[];
    const uint32_t smb = smem_u32(smraw);

    const int tid = threadIdx.x;
    const int numX = gridDim.x, numY = gridDim.y;
    const int bid = blockIdx.y * numX + blockIdx.x;
    const int strip = RASTER_G * numX;
    const int sIdx = bid / strip;
    const int rIdx = bid % strip;
    const int gRows = (numY - sIdx * RASTER_G) < RASTER_G ? (numY - sIdx * RASTER_G)
                                                          : RASTER_G;
    const int by = sIdx * RASTER_G + (rIdx % gRows);
    const int bx = rIdx / gRows;

    const int w = tid >> 5, lane = tid & 31;
    const int m0w = (w & 3) * 32, n0w = (w >> 2) * 64;

    const __nv_bfloat16* Abase = A  + (size_t)(by * 128) * Kp;
    const __nv_bfloat16* Bbase = Bw + (size_t)(bx * 128) * Kp;
    const int nch = Kp >> 6;

    auto load_stage = [&](int c, int s) {
        const uint32_t sa = smb + s * STAGE_BYTES;
        const uint32_t sb = sa + 16384;
        const int k0 = c * 64;
#pragma unroll
        for (int i = 0; i < 4; i++) {
            int idx = tid + i * 256;
            int row = idx >> 3, cc = idx & 7;
            uint32_t off = row * 128 + ((cc ^ (row & 7)) << 4);
            cp16(sa + off, Abase + (size_t)row * Kp + k0 + cc * 8);
            cp16(sb + off, Bbase + (size_t)row * Kp + k0 + cc * 8);
        }
        asm volatile("cp.async.commit_group;" ::: "memory");
    };

    float acc[2][8][4];
#pragma unroll
    for (int i = 0; i < 2; i++)
#pragma unroll
        for (int j = 0; j < 8; j++)
#pragma unroll
            for (int q = 0; q < 4; q++) acc[i][j][q] = 0.0f;

    const int a_row = m0w + (lane & 15);
    const int a_ccb = lane >> 4;
    const int b_row = n0w + (lane & 7) + ((lane >> 4) << 3);
    const int b_ccb = (lane >> 3) & 1;

    load_stage(0, 0);
    if (nch > 1) load_stage(1, 1);

    for (int c = 0; c < nch; c++) {
        const int s = c % NSTAGE;
        if (c + 1 < nch) asm volatile("cp.async.wait_group 1;" ::: "memory");
        else             asm volatile("cp.async.wait_group 0;" ::: "memory");
        __syncthreads();
        if (c + 2 < nch) load_stage(c + 2, (c + 2) % NSTAGE);

        const uint32_t sa = smb + s * STAGE_BYTES;
        const uint32_t sb = sa + 16384;
#pragma unroll
        for (int kk = 0; kk < 4; kk++) {
            uint32_t af[2][4];
#pragma unroll
            for (int mi = 0; mi < 2; mi++) {
                int row = a_row + mi * 16;
                int cc = kk * 2 + a_ccb;
                ldsm4(af[mi], sa + row * 128 + ((cc ^ (row & 7)) << 4));
            }
#pragma unroll
            for (int nj = 0; nj < 4; nj++) {
                uint32_t bf[4];
                int row = b_row + nj * 16;
                int cc = kk * 2 + b_ccb;
                ldsm4(bf, sb + row * 128 + ((cc ^ (row & 7)) << 4));
#pragma unroll
                for (int mi = 0; mi < 2; mi++) {
                    mma16816(acc[mi][nj * 2],     af[mi], bf[0], bf[1]);
                    mma16816(acc[mi][nj * 2 + 1], af[mi], bf[2], bf[3]);
                }
            }
        }
    }

    const int g = lane >> 2, t = lane & 3;
#pragma unroll
    for (int mi = 0; mi < 2; mi++) {
#pragma unroll
        for (int ni = 0; ni < 8; ni++) {
            const int col = bx * 128 + n0w + ni * 8 + 2 * t;
            const float b0 = __ldg(bias + col);
            const float b1 = __ldg(bias + col + 1);
            const int row0 = by * 128 + m0w + mi * 16 + g;
#pragma unroll
            for (int h = 0; h < 2; h++) {
                const int row = row0 + h * 8;
                float v0 = acc[mi][ni][2 * h]     + b0;
                float v1 = acc[mi][ni][2 * h + 1] + b1;
                if (MODE == 2) {
                    v0 = gelu_exact(v0); v1 = gelu_exact(v1);
                    __nv_bfloat16 h0 = __float2bfloat16(v0);
                    __nv_bfloat16 h1 = __float2bfloat16(v1);
                    __nv_bfloat16 l0 = __float2bfloat16(v0 - __bfloat162float(h0));
                    __nv_bfloat16 l1 = __float2bfloat16(v1 - __bfloat162float(h1));
                    uint32_t hp = pack_bf2(__bfloat162float(h0), __bfloat162float(h1));
                    uint32_t lp = pack_bf2(__bfloat162float(l0), __bfloat162float(l1));
                    const size_t rb = (size_t)row * (3 * KOUT) + col;
                    *(uint32_t*)(Cb + rb)            = hp;
                    *(uint32_t*)(Cb + rb + KOUT)     = lp;
                    *(uint32_t*)(Cb + rb + 2 * KOUT) = hp;
                } else {
                    const size_t base = (size_t)row * Nn + col;
                    if (MODE == 3) {
                        v0 += res1[base]     + res2[base];
                        v1 += res1[base + 1] + res2[base + 1];
                    }
                    *(float2*)(Cf + base) = make_float2(v0, v1);
                }
            }
        }
    }
}

// ---------------- split conversions -------------------------------------------
__global__ void asplit_kernel(const float* __restrict__ X, __nv_bfloat16* __restrict__ Y,
                              int M, int K)
{
    size_t i = (size_t)blockIdx.x * blockDim.x + threadIdx.x;
    if (i >= (size_t)M * K) return;
    int m = (int)(i / K), k = (int)(i % K);
    float v = X[i];
    __nv_bfloat16 hi = __float2bfloat16(v);
    __nv_bfloat16 lo = __float2bfloat16(v - __bfloat162float(hi));
    size_t rb = (size_t)m * 3 * K;
    Y[rb + k] = hi; Y[rb + K + k] = lo; Y[rb + 2 * K + k] = hi;
}

__global__ void wsplit_kernel(const float* __restrict__ W, __nv_bfloat16* __restrict__ Y,
                              int K, int N)
{
    size_t i = (size_t)blockIdx.x * blockDim.x + threadIdx.x;
    if (i >= (size_t)K * N) return;
    int n = (int)(i / K), k = (int)(i % K);
    float v = W[(size_t)k * N + n];
    __nv_bfloat16 hi = __float2bfloat16(v);
    __nv_bfloat16 lo = __float2bfloat16(v - __bfloat162float(hi));
    size_t rb = (size_t)n * 3 * K;
    Y[rb + k] = hi; Y[rb + K + k] = hi; Y[rb + 2 * K + k] = lo;
}

// ---------------- attention: 8 q/warp-iter, fused bf16x3 split output ----------
#define QPB 256
#define KPAD 65

__global__ void __launch_bounds__(256) attn_kernel(
    const float* __restrict__ Q, const float* __restrict__ K,
    const float* __restrict__ V, __nv_bfloat16* __restrict__ O)
{
    extern __shared__ float sm[];
    float* Ks = sm;                      // 256*65
    float* Vs = Ks + 256 * KPAD;         // 256*65
    float* qs = Vs + 256 * KPAD;         // 8 warps * 8 q * 64
    float* ps = qs + 8 * 8 * 64;         // 8 warps * 8 q * 256

    const int nchunk = TXQ / QPB;
    const int bid   = blockIdx.x;
    const int chunk = bid % nchunk;
    const int h     = (bid / nchunk) % NHEADS;
    const int b     = bid / (nchunk * NHEADS);

    const int tid  = threadIdx.x;
    const int lane = tid & 31;
    const int w    = tid >> 5;

    for (int i = tid; i < 256 * 16; i += 256) {
        int j  = i >> 4;
        int dq = (i & 15) * 4;
        size_t gbase = (size_t)(b * TXFK + j) * DMODEL + h * HDIM + dq;
        float4 kv = *(const float4*)(K + gbase);
        float4 vv = *(const float4*)(V + gbase);
        Ks[j * KPAD + dq + 0] = kv.x; Ks[j * KPAD + dq + 1] = kv.y;
        Ks[j * KPAD + dq + 2] = kv.z; Ks[j * KPAD + dq + 3] = kv.w;
        Vs[j * KPAD + dq + 0] = vv.x; Vs[j * KPAD + dq + 1] = vv.y;
        Vs[j * KPAD + dq + 2] = vv.z; Vs[j * KPAD + dq + 3] = vv.w;
    }
    __syncthreads();

    float* qw = qs + w * 8 * 64;
    float* pw = ps + w * 8 * 256;

    for (int qt = 0; qt < 4; qt++) {
        const size_t qrow0 = (size_t)b * TXQ + (size_t)chunk * QPB + w * 32 + qt * 8;
#pragma unroll
        for (int r = 0; r < 8; r++) {
            const float* qp = Q + (qrow0 + r) * DMODEL + h * HDIM;
            qw[r * 64 + lane]      = qp[lane];
            qw[r * 64 + lane + 32] = qp[lane + 32];
        }
        __syncwarp();

        float s[8][8];
#pragma unroll
        for (int r = 0; r < 8; r++)
#pragma unroll
            for (int c = 0; c < 8; c++) s[r][c] = 0.0f;

        for (int d = 0; d < 64; d += 2) {
            float ka[8], kb[8];
#pragma unroll
            for (int c = 0; c < 8; c++) {
                ka[c] = Ks[(lane + 32 * c) * KPAD + d];
                kb[c] = Ks[(lane + 32 * c) * KPAD + d + 1];
            }
#pragma unroll
            for (int r = 0; r < 8; r++) {
                float2 q2 = *(const float2*)&qw[r * 64 + d];
#pragma unroll
                for (int c = 0; c < 8; c++)
                    s[r][c] += q2.x * ka[c] + q2.y * kb[c];
            }
        }

#pragma unroll
        for (int r = 0; r < 8; r++) {
#pragma unroll
            for (int c = 0; c < 8; c++) s[r][c] *= ATT_SCALE;
            float mx = s[r][0];
#pragma unroll
            for (int c = 1; c < 8; c++) mx = fmaxf(mx, s[r][c]);
#pragma unroll
            for (int o = 16; o; o >>= 1) mx = fmaxf(mx, __shfl_xor_sync(~0u, mx, o));
            float sum = 0.0f;
#pragma unroll
            for (int c = 0; c < 8; c++) { s[r][c] = __expf(s[r][c] - mx); sum += s[r][c]; }
#pragma unroll
            for (int o = 16; o; o >>= 1) sum += __shfl_xor_sync(~0u, sum, o);
            float inv = 1.0f / sum;
#pragma unroll
            for (int c = 0; c < 8; c++) pw[r * 256 + lane + 32 * c] = s[r][c] * inv;
        }
        __syncwarp();

        float o0[8], o1[8];
#pragma unroll
        for (int r = 0; r < 8; r++) { o0[r] = 0.0f; o1[r] = 0.0f; }
        for (int j = 0; j < 256; j += 2) {
            float va0 = Vs[j * KPAD + lane];
            float va1 = Vs[j * KPAD + lane + 32];
            float vb0 = Vs[(j + 1) * KPAD + lane];
            float vb1 = Vs[(j + 1) * KPAD + lane + 32];
#pragma unroll
            for (int r = 0; r < 8; r++) {
                float2 p2 = *(const float2*)&pw[r * 256 + j];
                o0[r] += p2.x * va0 + p2.y * vb0;
                o1[r] += p2.x * va1 + p2.y * vb1;
            }
        }
        // fused [hi|lo|hi] split write (row width 3*DMODEL)
#pragma unroll
        for (int r = 0; r < 8; r++) {
            const size_t rb = (qrow0 + r) * (size_t)(3 * DMODEL) + h * HDIM;
            __nv_bfloat16 h0 = __float2bfloat16(o0[r]);
            __nv_bfloat16 l0 = __float2bfloat16(o0[r] - __bfloat162float(h0));
            __nv_bfloat16 h1 = __float2bfloat16(o1[r]);
            __nv_bfloat16 l1 = __float2bfloat16(o1[r] - __bfloat162float(h1));
            O[rb + lane]                   = h0;
            O[rb + DMODEL + lane]          = l0;
            O[rb + 2 * DMODEL + lane]      = h0;
            O[rb + lane + 32]              = h1;
            O[rb + DMODEL + lane + 32]     = l1;
            O[rb + 2 * DMODEL + lane + 32] = h1;
        }
        __syncwarp();
    }
}

// ---------------- LayerNorm -> split bf16 --------------------------------------
__global__ void __launch_bounds__(256) ln_split_kernel(
    const float* __restrict__ X, const float* __restrict__ gw,
    const float* __restrict__ bw, __nv_bfloat16* __restrict__ Y)
{
    const int row = blockIdx.x;
    const int t = threadIdx.x;
    float4 v = ((const float4*)(X + (size_t)row * DMODEL))[t];
    float s1 = v.x + v.y + v.z + v.w;
    float s2 = v.x * v.x + v.y * v.y + v.z * v.z + v.w * v.w;
#pragma unroll
    for (int o = 16; o; o >>= 1) {
        s1 += __shfl_xor_sync(~0u, s1, o);
        s2 += __shfl_xor_sync(~0u, s2, o);
    }
    __shared__ float r1[8], r2[8];
    const int w = t >> 5, lane = t & 31;
    if (lane == 0) { r1[w] = s1; r2[w] = s2; }
    __syncthreads();
    if (w == 0) {
        s1 = (lane < 8) ? r1[lane] : 0.0f;
        s2 = (lane < 8) ? r2[lane] : 0.0f;
#pragma unroll
        for (int o = 4; o; o >>= 1) {
            s1 += __shfl_xor_sync(~0u, s1, o);
            s2 += __shfl_xor_sync(~0u, s2, o);
        }
        if (lane == 0) { r1[0] = s1; r2[0] = s2; }
    }
    __syncthreads();
    const float mean = r1[0] * (1.0f / DMODEL);
    const float var  = r2[0] * (1.0f / DMODEL) - mean * mean;
    const float rstd = rsqrtf(var + 1e-5f);
    float4 g4 = ((const float4*)gw)[t];
    float4 b4 = ((const float4*)bw)[t];
    float vv[4];
    vv[0] = (v.x - mean) * rstd * g4.x + b4.x;
    vv[1] = (v.y - mean) * rstd * g4.y + b4.y;
    vv[2] = (v.z - mean) * rstd * g4.z + b4.z;
    vv[3] = (v.w - mean) * rstd * g4.w + b4.w;

    const size_t rb = (size_t)row * 3 * DMODEL;
    const int c = t * 4;
    uint32_t hp[2], lp[2];
#pragma unroll
    for (int jj = 0; jj < 2; jj++) {
        __nv_bfloat16 h0 = __float2bfloat16(vv[2*jj]);
        __nv_bfloat16 h1 = __float2bfloat16(vv[2*jj+1]);
        __nv_bfloat16 l0 = __float2bfloat16(vv[2*jj]   - __bfloat162float(h0));
        __nv_bfloat16 l1 = __float2bfloat16(vv[2*jj+1] - __bfloat162float(h1));
        hp[jj] = pack_bf2(__bfloat162float(h0), __bfloat162float(h1));
        lp[jj] = pack_bf2(__bfloat162float(l0), __bfloat162float(l1));
    }
    *(uint2*)(Y + rb + c)              = make_uint2(hp[0], hp[1]);
    *(uint2*)(Y + rb + DMODEL + c)     = make_uint2(lp[0], lp[1]);
    *(uint2*)(Y + rb + 2 * DMODEL + c) = make_uint2(hp[0], hp[1]);
}

// ---------------- launch -------------------------------------------------------
extern "C" void kernel_launch(void* const* d_in, const int* in_sizes, int n_in,
                              void* d_out, int out_size)
{
    const float* x    = (const float*)d_in[0];
    const float* xf   = (const float*)d_in[1];
    const float* Wq   = (const float*)d_in[2];
    const float* bq   = (const float*)d_in[3];
    const float* Wk   = (const float*)d_in[4];
    const float* bk   = (const float*)d_in[5];
    const float* Wv   = (const float*)d_in[6];
    const float* bv   = (const float*)d_in[7];
    const float* Wo   = (const float*)d_in[8];
    const float* bo   = (const float*)d_in[9];
    const float* ln_g = (const float*)d_in[10];
    const float* ln_b = (const float*)d_in[11];
    const float* W1   = (const float*)d_in[12];
    const float* b1   = (const float*)d_in[13];
    const float* W2   = (const float*)d_in[14];
    const float* b2   = (const float*)d_in[15];
    float* out = (float*)d_out;

    float *q, *k, *v, *res;
    __nv_bfloat16 *xs, *xfs, *attns, *lns, *hs, *wq, *wk, *wv, *wo, *w1, *w2;
    cudaGetSymbolAddress((void**)&q,     g_q);
    cudaGetSymbolAddress((void**)&k,     g_k);
    cudaGetSymbolAddress((void**)&v,     g_v);
    cudaGetSymbolAddress((void**)&res,   g_res);
    cudaGetSymbolAddress((void**)&xs,    g_xs);
    cudaGetSymbolAddress((void**)&xfs,   g_xfs);
    cudaGetSymbolAddress((void**)&attns, g_attns);
    cudaGetSymbolAddress((void**)&lns,   g_lns);
    cudaGetSymbolAddress((void**)&hs,    g_hs);
    cudaGetSymbolAddress((void**)&wq,    g_wq);
    cudaGetSymbolAddress((void**)&wk,    g_wk);
    cudaGetSymbolAddress((void**)&wv,    g_wv);
    cudaGetSymbolAddress((void**)&wo,    g_wo);
    cudaGetSymbolAddress((void**)&w1,    g_w1);
    cudaGetSymbolAddress((void**)&w2,    g_w2);

    const int GEMM_SMEM = NSTAGE * STAGE_BYTES;   // 96KB
    cudaFuncSetAttribute(mma_gemm<0>, cudaFuncAttributeMaxDynamicSharedMemorySize, GEMM_SMEM);
    cudaFuncSetAttribute(mma_gemm<2>, cudaFuncAttributeMaxDynamicSharedMemorySize, GEMM_SMEM);
    cudaFuncSetAttribute(mma_gemm<3>, cudaFuncAttributeMaxDynamicSharedMemorySize, GEMM_SMEM);
    const size_t attn_smem =
        (size_t)(2 * 256 * KPAD + 8 * 8 * 64 + 8 * 8 * 256) * sizeof(float);
    cudaFuncSetAttribute(attn_kernel, cudaFuncAttributeMaxDynamicSharedMemorySize,
                         (int)attn_smem);

    dim3 blk(256);
    auto cdiv = [](size_t a, size_t b) { return (unsigned)((a + b - 1) / b); };

    // weight transposition + splits
    wsplit_kernel<<<cdiv((size_t)DMODEL * DMODEL, 256), blk>>>(Wq, wq, DMODEL, DMODEL);
    wsplit_kernel<<<cdiv((size_t)DTEXT  * DMODEL, 256), blk>>>(Wk, wk, DTEXT,  DMODEL);
    wsplit_kernel<<<cdiv((size_t)DTEXT  * DMODEL, 256), blk>>>(Wv, wv, DTEXT,  DMODEL);
    wsplit_kernel<<<cdiv((size_t)DMODEL * DMODEL, 256), blk>>>(Wo, wo, DMODEL, DMODEL);
    wsplit_kernel<<<cdiv((size_t)DMODEL * DFF,    256), blk>>>(W1, w1, DMODEL, DFF);
    wsplit_kernel<<<cdiv((size_t)DFF    * DMODEL, 256), blk>>>(W2, w2, DFF,    DMODEL);
    // activation splits
    asplit_kernel<<<cdiv((size_t)MQ  * DMODEL, 256), blk>>>(x,  xs,  MQ,  DMODEL);
    asplit_kernel<<<cdiv((size_t)MKV * DTEXT,  256), blk>>>(xf, xfs, MKV, DTEXT);

    // Q = x@Wq + bq ; K/V = xf@W{k,v} + b
    mma_gemm<0><<<dim3(DMODEL / 128, MQ / 128), blk, GEMM_SMEM>>>(
        DMODEL, 3 * DMODEL, xs, wq, bq, nullptr, nullptr, q, nullptr, 0);
    mma_gemm<0><<<dim3(DMODEL / 128, MKV / 128), blk, GEMM_SMEM>>>(
        DMODEL, 3 * DTEXT, xfs, wk, bk, nullptr, nullptr, k, nullptr, 0);
    mma_gemm<0><<<dim3(DMODEL / 128, MKV / 128), blk, GEMM_SMEM>>>(
        DMODEL, 3 * DTEXT, xfs, wv, bv, nullptr, nullptr, v, nullptr, 0);

    // attention (writes split-bf16 output directly)
    attn_kernel<<<BDIM * NHEADS * (TXQ / QPB), blk, attn_smem>>>(q, k, v, attns);

    // out = attn@Wo + bo (residual base)
    mma_gemm<0><<<dim3(DMODEL / 128, MQ / 128), blk, GEMM_SMEM>>>(
        DMODEL, 3 * DMODEL, attns, wo, bo, nullptr, nullptr, res, nullptr, 0);

    // LayerNorm -> split
    ln_split_kernel<<<MQ, blk>>>(res, ln_g, ln_b, lns);

    // h = GELU(ln@W1 + b1) -> split directly
    mma_gemm<2><<<dim3(DFF / 128, MQ / 128), blk, GEMM_SMEM>>>(
        DFF, 3 * DMODEL, lns, w1, b1, nullptr, nullptr, nullptr, hs, DFF);

    // final = h@W2 + b2 + res + x
    mma_gemm<3><<<dim3(DMODEL / 128, MQ / 128), blk, GEMM_SMEM>>>(
        DMODEL, 3 * DFF, hs, w2, b2, res, x, out, nullptr, 0);
}

// round 10
// speedup vs baseline: 1.5664x; 1.3720x over previous
#include <cuda_runtime.h>
#include <cuda_fp16.h>
#include <math.h>
#include <stdint.h>

#define BDIM   4
#define TXQ    4096
#define TXFK   256
#define DMODEL 1024
#define DTEXT  768
#define NHEADS 16
#define HDIM   64
#define MQ     (BDIM*TXQ)     // 16384
#define MKV    (BDIM*TXFK)    // 1024
#define DFF    4096
#define ATT_SCALE 0.125f

// ---------------- scratch (device globals) -----------------------------------
__device__ float g_q   [(size_t)MQ  * DMODEL];
__device__ float g_k   [(size_t)MKV * DMODEL];
__device__ float g_v   [(size_t)MKV * DMODEL];
__device__ float g_res [(size_t)MQ  * DMODEL];

// fp16x2 split: activations [hi | lo] (2K wide), weights transposed [N,K] fp16
__device__ __half g_xs   [(size_t)MQ  * 2 * DMODEL];
__device__ __half g_xfs  [(size_t)MKV * 2 * DTEXT];
__device__ __half g_attns[(size_t)MQ  * 2 * DMODEL];
__device__ __half g_lns  [(size_t)MQ  * 2 * DMODEL];
__device__ __half g_hs   [(size_t)MQ  * 2 * DFF];
__device__ __half g_wq   [(size_t)DMODEL * DMODEL];
__device__ __half g_wk   [(size_t)DMODEL * DTEXT];
__device__ __half g_wv   [(size_t)DMODEL * DTEXT];
__device__ __half g_wo   [(size_t)DMODEL * DMODEL];
__device__ __half g_w1   [(size_t)DFF    * DMODEL];
__device__ __half g_w2   [(size_t)DMODEL * DFF];

__device__ __forceinline__ float gelu_exact(float v) {
    return 0.5f * v * (1.0f + erff(v * 0.7071067811865476f));
}

// ---------------- PTX helpers (target-portable, sm_80+) -----------------------
__device__ __forceinline__ uint32_t smem_u32(const void* p) {
    uint32_t a;
    asm("{ .reg .u64 t; cvta.to.shared.u64 t, %1; cvt.u32.u64 %0, t; }"
        : "=r"(a) : "l"(p));
    return a;
}
__device__ __forceinline__ void cp16(uint32_t s, const void* g) {
    asm volatile("cp.async.cg.shared.global [%0], [%1], 16;" :: "r"(s), "l"(g));
}
__device__ __forceinline__ void ldsm4(uint32_t* r, uint32_t a) {
    asm volatile("ldmatrix.sync.aligned.m8n8.x4.shared.b16 {%0,%1,%2,%3}, [%4];"
        : "=r"(r[0]), "=r"(r[1]), "=r"(r[2]), "=r"(r[3]) : "r"(a));
}
__device__ __forceinline__ void mma16816(float* c, const uint32_t* a,
                                         uint32_t b0, uint32_t b1) {
    asm volatile(
        "mma.sync.aligned.m16n8k16.row.col.f32.f16.f16.f32 "
        "{%0,%1,%2,%3}, {%4,%5,%6,%7}, {%8,%9}, {%0,%1,%2,%3};"
        : "+f"(c[0]), "+f"(c[1]), "+f"(c[2]), "+f"(c[3])
        : "r"(a[0]), "r"(a[1]), "r"(a[2]), "r"(a[3]), "r"(b0), "r"(b1));
}
__device__ __forceinline__ uint32_t pack_h2(float a, float b) {
    __half2 t = __floats2half2_rn(a, b);
    uint32_t u; memcpy(&u, &t, 4); return u;
}
__device__ __forceinline__ void split_h(float v, __half& hi, __half& lo) {
    hi = __float2half_rn(v);
    lo = __float2half_rn(v - __half2float(hi));
}

// ---------------- fp16x2 HMMA GEMM --------------------------------------------
// C[M,N] = (A_hi + A_lo)[M,K] @ B[N,K]^T. A stored [M, 2K] = [hi | lo], fp16.
// B stored [N, K] fp16 (hi only). BM=BN=128, BK=64; B tile loaded ONCE per
// chunk, used for both hi and lo passes. 256 thr, 8 warps, warp tile 32x64.
// 2-stage cp.async (48KB/stage, 96KB total, occ 2). Raster swizzle G=16.
// MODE 0: Cf = acc + bias
// MODE 2: split(gelu(acc + bias)) -> Cb [hi|lo], row width 2*KOUT
// MODE 3: Cf = acc + bias + res1 + res2
#define STAGE_BYTES 49152       // 16KB A_hi + 16KB A_lo + 16KB B
#define NSTAGE 2
#define RASTER_G 16

template<int MODE>
__global__ void __launch_bounds__(256, 2) mma_gemm(
    int Nn, int Kk,
    const __half* __restrict__ A, const __half* __restrict__ Bw,
    const float* __restrict__ bias,
    const float* __restrict__ res1, const float* __restrict__ res2,
    float* __restrict__ Cf, __half* __restrict__ Cb, int KOUT)
{
    extern __shared__ char smraw[];
    const uint32_t smb = smem_u32(smraw);

    const int tid = threadIdx.x;
    const int numX = gridDim.x, numY = gridDim.y;
    const int bid = blockIdx.y * numX + blockIdx.x;
    const int strip = RASTER_G * numX;
    const int sIdx = bid / strip;
    const int rIdx = bid % strip;
    const int gRows = (numY - sIdx * RASTER_G) < RASTER_G ? (numY - sIdx * RASTER_G)
                                                          : RASTER_G;
    const int by = sIdx * RASTER_G + (rIdx % gRows);
    const int bx = rIdx / gRows;

    const int w = tid >> 5, lane = tid & 31;
    const int m0w = (w & 3) * 32, n0w = (w >> 2) * 64;

    const int K2 = 2 * Kk;
    const __half* Abase = A  + (size_t)(by * 128) * K2;
    const __half* Bbase = Bw + (size_t)(bx * 128) * Kk;
    const int nch = Kk >> 6;

    auto load_stage = [&](int c, int s) {
        const uint32_t sah = smb + s * STAGE_BYTES;
        const uint32_t sal = sah + 16384;
        const uint32_t sb  = sah + 32768;
        const int k0 = c * 64;
#pragma unroll
        for (int i = 0; i < 4; i++) {      // 1024 chunks each region
            int idx = tid + i * 256;
            int row = idx >> 3, cc = idx & 7;
            uint32_t off = row * 128 + ((cc ^ (row & 7)) << 4);
            cp16(sah + off, Abase + (size_t)row * K2 + k0 + cc * 8);
            cp16(sal + off, Abase + (size_t)row * K2 + Kk + k0 + cc * 8);
            cp16(sb  + off, Bbase + (size_t)row * Kk + k0 + cc * 8);
        }
        asm volatile("cp.async.commit_group;" ::: "memory");
    };

    float acc[2][8][4];
#pragma unroll
    for (int i = 0; i < 2; i++)
#pragma unroll
        for (int j = 0; j < 8; j++)
#pragma unroll
            for (int q = 0; q < 4; q++) acc[i][j][q] = 0.0f;

    const int a_row = m0w + (lane & 15);
    const int a_ccb = lane >> 4;
    const int b_row = n0w + (lane & 7) + ((lane >> 4) << 3);
    const int b_ccb = (lane >> 3) & 1;

    load_stage(0, 0);
    if (nch > 1) load_stage(1, 1);

    for (int c = 0; c < nch; c++) {
        const int s = c & 1;
        if (c + 1 < nch) asm volatile("cp.async.wait_group 1;" ::: "memory");
        else             asm volatile("cp.async.wait_group 0;" ::: "memory");
        __syncthreads();

        const uint32_t sah = smb + s * STAGE_BYTES;
        const uint32_t sal = sah + 16384;
        const uint32_t sb  = sah + 32768;
#pragma unroll
        for (int kk = 0; kk < 4; kk++) {
            uint32_t ah[2][4], al[2][4];
#pragma unroll
            for (int mi = 0; mi < 2; mi++) {
                int row = a_row + mi * 16;
                int cc = kk * 2 + a_ccb;
                uint32_t off = row * 128 + ((cc ^ (row & 7)) << 4);
                ldsm4(ah[mi], sah + off);
                ldsm4(al[mi], sal + off);
            }
#pragma unroll
            for (int nj = 0; nj < 4; nj++) {
                uint32_t bf[4];
                int row = b_row + nj * 16;
                int cc = kk * 2 + b_ccb;
                ldsm4(bf, sb + row * 128 + ((cc ^ (row & 7)) << 4));
#pragma unroll
                for (int mi = 0; mi < 2; mi++) {
                    mma16816(acc[mi][nj * 2],     ah[mi], bf[0], bf[1]);
                    mma16816(acc[mi][nj * 2 + 1], ah[mi], bf[2], bf[3]);
                    mma16816(acc[mi][nj * 2],     al[mi], bf[0], bf[1]);
                    mma16816(acc[mi][nj * 2 + 1], al[mi], bf[2], bf[3]);
                }
            }
        }
        __syncthreads();
        if (c + 2 < nch) load_stage(c + 2, s);
    }

    const int g = lane >> 2, t = lane & 3;
#pragma unroll
    for (int mi = 0; mi < 2; mi++) {
#pragma unroll
        for (int ni = 0; ni < 8; ni++) {
            const int col = bx * 128 + n0w + ni * 8 + 2 * t;
            const float b0 = __ldg(bias + col);
            const float b1 = __ldg(bias + col + 1);
            const int row0 = by * 128 + m0w + mi * 16 + g;
#pragma unroll
            for (int h = 0; h < 2; h++) {
                const int row = row0 + h * 8;
                float v0 = acc[mi][ni][2 * h]     + b0;
                float v1 = acc[mi][ni][2 * h + 1] + b1;
                if (MODE == 2) {
                    v0 = gelu_exact(v0); v1 = gelu_exact(v1);
                    __half h0, l0, h1, l1;
                    split_h(v0, h0, l0);
                    split_h(v1, h1, l1);
                    const size_t rb = (size_t)row * (2 * KOUT) + col;
                    *(uint32_t*)(Cb + rb)        = pack_h2(__half2float(h0), __half2float(h1));
                    *(uint32_t*)(Cb + rb + KOUT) = pack_h2(__half2float(l0), __half2float(l1));
                } else {
                    const size_t base = (size_t)row * Nn + col;
                    if (MODE == 3) {
                        v0 += res1[base]     + res2[base];
                        v1 += res1[base + 1] + res2[base + 1];
                    }
                    *(float2*)(Cf + base) = make_float2(v0, v1);
                }
            }
        }
    }
}

// ---------------- split conversions -------------------------------------------
// activation: X[M,K] fp32 -> Y[M,2K] fp16 [hi | lo]
__global__ void asplit_kernel(const float* __restrict__ X, __half* __restrict__ Y,
                              int M, int K)
{
    size_t i = (size_t)blockIdx.x * blockDim.x + threadIdx.x;
    if (i >= (size_t)M * K) return;
    int m = (int)(i / K), k = (int)(i % K);
    __half hi, lo;
    split_h(X[i], hi, lo);
    size_t rb = (size_t)m * 2 * K;
    Y[rb + k] = hi; Y[rb + K + k] = lo;
}

// weight: W[K,N] fp32 -> Y[N,K] fp16 (transpose + convert)
__global__ void wsplit_kernel(const float* __restrict__ W, __half* __restrict__ Y,
                              int K, int N)
{
    size_t i = (size_t)blockIdx.x * blockDim.x + threadIdx.x;
    if (i >= (size_t)K * N) return;
    int n = (int)(i / K), k = (int)(i % K);
    Y[(size_t)n * K + k] = __float2half_rn(W[(size_t)k * N + n]);
}

// ---------------- attention: 8 q/warp-iter, fused fp16x2 split output ----------
#define QPB 256
#define KPAD 65

__global__ void __launch_bounds__(256) attn_kernel(
    const float* __restrict__ Q, const float* __restrict__ K,
    const float* __restrict__ V, __half* __restrict__ O)
{
    extern __shared__ float sm[];
    float* Ks = sm;                      // 256*65
    float* Vs = Ks + 256 * KPAD;         // 256*65
    float* qs = Vs + 256 * KPAD;         // 8 warps * 8 q * 64
    float* ps = qs + 8 * 8 * 64;         // 8 warps * 8 q * 256

    const int nchunk = TXQ / QPB;
    const int bid   = blockIdx.x;
    const int chunk = bid % nchunk;
    const int h     = (bid / nchunk) % NHEADS;
    const int b     = bid / (nchunk * NHEADS);

    const int tid  = threadIdx.x;
    const int lane = tid & 31;
    const int w    = tid >> 5;

    for (int i = tid; i < 256 * 16; i += 256) {
        int j  = i >> 4;
        int dq = (i & 15) * 4;
        size_t gbase = (size_t)(b * TXFK + j) * DMODEL + h * HDIM + dq;
        float4 kv = *(const float4*)(K + gbase);
        float4 vv = *(const float4*)(V + gbase);
        Ks[j * KPAD + dq + 0] = kv.x; Ks[j * KPAD + dq + 1] = kv.y;
        Ks[j * KPAD + dq + 2] = kv.z; Ks[j * KPAD + dq + 3] = kv.w;
        Vs[j * KPAD + dq + 0] = vv.x; Vs[j * KPAD + dq + 1] = vv.y;
        Vs[j * KPAD + dq + 2] = vv.z; Vs[j * KPAD + dq + 3] = vv.w;
    }
    __syncthreads();

    float* qw = qs + w * 8 * 64;
    float* pw = ps + w * 8 * 256;

    for (int qt = 0; qt < 4; qt++) {
        const size_t qrow0 = (size_t)b * TXQ + (size_t)chunk * QPB + w * 32 + qt * 8;
#pragma unroll
        for (int r = 0; r < 8; r++) {
            const float* qp = Q + (qrow0 + r) * DMODEL + h * HDIM;
            qw[r * 64 + lane]      = qp[lane];
            qw[r * 64 + lane + 32] = qp[lane + 32];
        }
        __syncwarp();

        float s[8][8];
#pragma unroll
        for (int r = 0; r < 8; r++)
#pragma unroll
            for (int c = 0; c < 8; c++) s[r][c] = 0.0f;

        for (int d = 0; d < 64; d += 2) {
            float ka[8], kb[8];
#pragma unroll
            for (int c = 0; c < 8; c++) {
                ka[c] = Ks[(lane + 32 * c) * KPAD + d];
                kb[c] = Ks[(lane + 32 * c) * KPAD + d + 1];
            }
#pragma unroll
            for (int r = 0; r < 8; r++) {
                float2 q2 = *(const float2*)&qw[r * 64 + d];
#pragma unroll
                for (int c = 0; c < 8; c++)
                    s[r][c] += q2.x * ka[c] + q2.y * kb[c];
            }
        }

#pragma unroll
        for (int r = 0; r < 8; r++) {
#pragma unroll
            for (int c = 0; c < 8; c++) s[r][c] *= ATT_SCALE;
            float mx = s[r][0];
#pragma unroll
            for (int c = 1; c < 8; c++) mx = fmaxf(mx, s[r][c]);
#pragma unroll
            for (int o = 16; o; o >>= 1) mx = fmaxf(mx, __shfl_xor_sync(~0u, mx, o));
            float sum = 0.0f;
#pragma unroll
            for (int c = 0; c < 8; c++) { s[r][c] = __expf(s[r][c] - mx); sum += s[r][c]; }
#pragma unroll
            for (int o = 16; o; o >>= 1) sum += __shfl_xor_sync(~0u, sum, o);
            float inv = 1.0f / sum;
#pragma unroll
            for (int c = 0; c < 8; c++) pw[r * 256 + lane + 32 * c] = s[r][c] * inv;
        }
        __syncwarp();

        float o0[8], o1[8];
#pragma unroll
        for (int r = 0; r < 8; r++) { o0[r] = 0.0f; o1[r] = 0.0f; }
        for (int j = 0; j < 256; j += 2) {
            float va0 = Vs[j * KPAD + lane];
            float va1 = Vs[j * KPAD + lane + 32];
            float vb0 = Vs[(j + 1) * KPAD + lane];
            float vb1 = Vs[(j + 1) * KPAD + lane + 32];
#pragma unroll
            for (int r = 0; r < 8; r++) {
                float2 p2 = *(const float2*)&pw[r * 256 + j];
                o0[r] += p2.x * va0 + p2.y * vb0;
                o1[r] += p2.x * va1 + p2.y * vb1;
            }
        }
        // fused [hi|lo] split write (row width 2*DMODEL)
#pragma unroll
        for (int r = 0; r < 8; r++) {
            const size_t rb = (qrow0 + r) * (size_t)(2 * DMODEL) + h * HDIM;
            __half h0, l0, h1, l1;
            split_h(o0[r], h0, l0);
            split_h(o1[r], h1, l1);
            O[rb + lane]               = h0;
            O[rb + DMODEL + lane]      = l0;
            O[rb + lane + 32]          = h1;
            O[rb + DMODEL + lane + 32] = l1;
        }
        __syncwarp();
    }
}

// ---------------- LayerNorm -> split fp16 --------------------------------------
__global__ void __launch_bounds__(256) ln_split_kernel(
    const float* __restrict__ X, const float* __restrict__ gw,
    const float* __restrict__ bw, __half* __restrict__ Y)
{
    const int row = blockIdx.x;
    const int t = threadIdx.x;
    float4 v = ((const float4*)(X + (size_t)row * DMODEL))[t];
    float s1 = v.x + v.y + v.z + v.w;
    float s2 = v.x * v.x + v.y * v.y + v.z * v.z + v.w * v.w;
#pragma unroll
    for (int o = 16; o; o >>= 1) {
        s1 += __shfl_xor_sync(~0u, s1, o);
        s2 += __shfl_xor_sync(~0u, s2, o);
    }
    __shared__ float r1[8], r2[8];
    const int w = t >> 5, lane = t & 31;
    if (lane == 0) { r1[w] = s1; r2[w] = s2; }
    __syncthreads();
    if (w == 0) {
        s1 = (lane < 8) ? r1[lane] : 0.0f;
        s2 = (lane < 8) ? r2[lane] : 0.0f;
#pragma unroll
        for (int o = 4; o; o >>= 1) {
            s1 += __shfl_xor_sync(~0u, s1, o);
            s2 += __shfl_xor_sync(~0u, s2, o);
        }
        if (lane == 0) { r1[0] = s1; r2[0] = s2; }
    }
    __syncthreads();
    const float mean = r1[0] * (1.0f / DMODEL);
    const float var  = r2[0] * (1.0f / DMODEL) - mean * mean;
    const float rstd = rsqrtf(var + 1e-5f);
    float4 g4 = ((const float4*)gw)[t];
    float4 b4 = ((const float4*)bw)[t];
    float vv[4];
    vv[0] = (v.x - mean) * rstd * g4.x + b4.x;
    vv[1] = (v.y - mean) * rstd * g4.y + b4.y;
    vv[2] = (v.z - mean) * rstd * g4.z + b4.z;
    vv[3] = (v.w - mean) * rstd * g4.w + b4.w;

    const size_t rb = (size_t)row * 2 * DMODEL;
    const int c = t * 4;
    uint32_t hp[2], lp[2];
#pragma unroll
    for (int jj = 0; jj < 2; jj++) {
        __half h0, l0, h1, l1;
        split_h(vv[2*jj],   h0, l0);
        split_h(vv[2*jj+1], h1, l1);
        hp[jj] = pack_h2(__half2float(h0), __half2float(h1));
        lp[jj] = pack_h2(__half2float(l0), __half2float(l1));
    }
    *(uint2*)(Y + rb + c)          = make_uint2(hp[0], hp[1]);
    *(uint2*)(Y + rb + DMODEL + c) = make_uint2(lp[0], lp[1]);
}

// ---------------- launch -------------------------------------------------------
extern "C" void kernel_launch(void* const* d_in, const int* in_sizes, int n_in,
                              void* d_out, int out_size)
{
    const float* x    = (const float*)d_in[0];
    const float* xf   = (const float*)d_in[1];
    const float* Wq   = (const float*)d_in[2];
    const float* bq   = (const float*)d_in[3];
    const float* Wk   = (const float*)d_in[4];
    const float* bk   = (const float*)d_in[5];
    const float* Wv   = (const float*)d_in[6];
    const float* bv   = (const float*)d_in[7];
    const float* Wo   = (const float*)d_in[8];
    const float* bo   = (const float*)d_in[9];
    const float* ln_g = (const float*)d_in[10];
    const float* ln_b = (const float*)d_in[11];
    const float* W1   = (const float*)d_in[12];
    const float* b1   = (const float*)d_in[13];
    const float* W2   = (const float*)d_in[14];
    const float* b2   = (const float*)d_in[15];
    float* out = (float*)d_out;

    float *q, *k, *v, *res;
    __half *xs, *xfs, *attns, *lns, *hs, *wq, *wk, *wv, *wo, *w1, *w2;
    cudaGetSymbolAddress((void**)&q,     g_q);
    cudaGetSymbolAddress((void**)&k,     g_k);
    cudaGetSymbolAddress((void**)&v,     g_v);
    cudaGetSymbolAddress((void**)&res,   g_res);
    cudaGetSymbolAddress((void**)&xs,    g_xs);
    cudaGetSymbolAddress((void**)&xfs,   g_xfs);
    cudaGetSymbolAddress((void**)&attns, g_attns);
    cudaGetSymbolAddress((void**)&lns,   g_lns);
    cudaGetSymbolAddress((void**)&hs,    g_hs);
    cudaGetSymbolAddress((void**)&wq,    g_wq);
    cudaGetSymbolAddress((void**)&wk,    g_wk);
    cudaGetSymbolAddress((void**)&wv,    g_wv);
    cudaGetSymbolAddress((void**)&wo,    g_wo);
    cudaGetSymbolAddress((void**)&w1,    g_w1);
    cudaGetSymbolAddress((void**)&w2,    g_w2);

    const int GEMM_SMEM = NSTAGE * STAGE_BYTES;   // 96KB
    cudaFuncSetAttribute(mma_gemm<0>, cudaFuncAttributeMaxDynamicSharedMemorySize, GEMM_SMEM);
    cudaFuncSetAttribute(mma_gemm<2>, cudaFuncAttributeMaxDynamicSharedMemorySize, GEMM_SMEM);
    cudaFuncSetAttribute(mma_gemm<3>, cudaFuncAttributeMaxDynamicSharedMemorySize, GEMM_SMEM);
    const size_t attn_smem =
        (size_t)(2 * 256 * KPAD + 8 * 8 * 64 + 8 * 8 * 256) * sizeof(float);
    cudaFuncSetAttribute(attn_kernel, cudaFuncAttributeMaxDynamicSharedMemorySize,
                         (int)attn_smem);

    dim3 blk(256);
    auto cdiv = [](size_t a, size_t b) { return (unsigned)((a + b - 1) / b); };

    // weight transpose+convert
    wsplit_kernel<<<cdiv((size_t)DMODEL * DMODEL, 256), blk>>>(Wq, wq, DMODEL, DMODEL);
    wsplit_kernel<<<cdiv((size_t)DTEXT  * DMODEL, 256), blk>>>(Wk, wk, DTEXT,  DMODEL);
    wsplit_kernel<<<cdiv((size_t)DTEXT  * DMODEL, 256), blk>>>(Wv, wv, DTEXT,  DMODEL);
    wsplit_kernel<<<cdiv((size_t)DMODEL * DMODEL, 256), blk>>>(Wo, wo, DMODEL, DMODEL);
    wsplit_kernel<<<cdiv((size_t)DMODEL * DFF,    256), blk>>>(W1, w1, DMODEL, DFF);
    wsplit_kernel<<<cdiv((size_t)DFF    * DMODEL, 256), blk>>>(W2, w2, DFF,    DMODEL);
    // activation splits
    asplit_kernel<<<cdiv((size_t)MQ  * DMODEL, 256), blk>>>(x,  xs,  MQ,  DMODEL);
    asplit_kernel<<<cdiv((size_t)MKV * DTEXT,  256), blk>>>(xf, xfs, MKV, DTEXT);

    // Q = x@Wq + bq ; K/V = xf@W{k,v} + b
    mma_gemm<0><<<dim3(DMODEL / 128, MQ / 128), blk, GEMM_SMEM>>>(
        DMODEL, DMODEL, xs, wq, bq, nullptr, nullptr, q, nullptr, 0);
    mma_gemm<0><<<dim3(DMODEL / 128, MKV / 128), blk, GEMM_SMEM>>>(
        DMODEL, DTEXT, xfs, wk, bk, nullptr, nullptr, k, nullptr, 0);
    mma_gemm<0><<<dim3(DMODEL / 128, MKV / 128), blk, GEMM_SMEM>>>(
        DMODEL, DTEXT, xfs, wv, bv, nullptr, nullptr, v, nullptr, 0);

    // attention (writes split-fp16 output directly)
    attn_kernel<<<BDIM * NHEADS * (TXQ / QPB), blk, attn_smem>>>(q, k, v, attns);

    // out = attn@Wo + bo (residual base)
    mma_gemm<0><<<dim3(DMODEL / 128, MQ / 128), blk, GEMM_SMEM>>>(
        DMODEL, DMODEL, attns, wo, bo, nullptr, nullptr, res, nullptr, 0);

    // LayerNorm -> split
    ln_split_kernel<<<MQ, blk>>>(res, ln_g, ln_b, lns);

    // h = GELU(ln@W1 + b1) -> split directly
    mma_gemm<2><<<dim3(DFF / 128, MQ / 128), blk, GEMM_SMEM>>>(
        DFF, DMODEL, lns, w1, b1, nullptr, nullptr, nullptr, hs, DFF);

    // final = h@W2 + b2 + res + x
    mma_gemm<3><<<dim3(DMODEL / 128, MQ / 128), blk, GEMM_SMEM>>>(
        DMODEL, DFF, hs, w2, b2, res, x, out, nullptr, 0);
}

// round 11
// speedup vs baseline: 2.2724x; 1.4507x over previous
#include <cuda_runtime.h>
#include <cuda_fp16.h>
#include <math.h>
#include <stdint.h>

#define BDIM   4
#define TXQ    4096
#define TXFK   256
#define DMODEL 1024
#define DTEXT  768
#define NHEADS 16
#define HDIM   64
#define MQ     (BDIM*TXQ)     // 16384
#define MKV    (BDIM*TXFK)    // 1024
#define DFF    4096
#define ATT_SCALE 0.125f

// ---------------- scratch (device globals) -----------------------------------
__device__ float g_q   [(size_t)MQ  * DMODEL];
__device__ float g_k   [(size_t)MKV * DMODEL];
__device__ float g_v   [(size_t)MKV * DMODEL];
__device__ float g_res [(size_t)MQ  * DMODEL];

// pure fp16: activations [M,K], weights transposed [N,K]
__device__ __half g_xs   [(size_t)MQ  * DMODEL];
__device__ __half g_xfs  [(size_t)MKV * DTEXT];
__device__ __half g_attns[(size_t)MQ  * DMODEL];
__device__ __half g_lns  [(size_t)MQ  * DMODEL];
__device__ __half g_hs   [(size_t)MQ  * DFF];
__device__ __half g_wq   [(size_t)DMODEL * DMODEL];
__device__ __half g_wk   [(size_t)DMODEL * DTEXT];
__device__ __half g_wv   [(size_t)DMODEL * DTEXT];
__device__ __half g_wo   [(size_t)DMODEL * DMODEL];
__device__ __half g_w1   [(size_t)DFF    * DMODEL];
__device__ __half g_w2   [(size_t)DMODEL * DFF];

__device__ __forceinline__ float gelu_exact(float v) {
    return 0.5f * v * (1.0f + erff(v * 0.7071067811865476f));
}

// ---------------- PTX helpers (target-portable, sm_80+) -----------------------
__device__ __forceinline__ uint32_t smem_u32(const void* p) {
    uint32_t a;
    asm("{ .reg .u64 t; cvta.to.shared.u64 t, %1; cvt.u32.u64 %0, t; }"
        : "=r"(a) : "l"(p));
    return a;
}
__device__ __forceinline__ void cp16(uint32_t s, const void* g) {
    asm volatile("cp.async.cg.shared.global [%0], [%1], 16;" :: "r"(s), "l"(g));
}
__device__ __forceinline__ void ldsm4(uint32_t* r, uint32_t a) {
    asm volatile("ldmatrix.sync.aligned.m8n8.x4.shared.b16 {%0,%1,%2,%3}, [%4];"
        : "=r"(r[0]), "=r"(r[1]), "=r"(r[2]), "=r"(r[3]) : "r"(a));
}
__device__ __forceinline__ void mma16816(float* c, const uint32_t* a,
                                         uint32_t b0, uint32_t b1) {
    asm volatile(
        "mma.sync.aligned.m16n8k16.row.col.f32.f16.f16.f32 "
        "{%0,%1,%2,%3}, {%4,%5,%6,%7}, {%8,%9}, {%0,%1,%2,%3};"
        : "+f"(c[0]), "+f"(c[1]), "+f"(c[2]), "+f"(c[3])
        : "r"(a[0]), "r"(a[1]), "r"(a[2]), "r"(a[3]), "r"(b0), "r"(b1));
}
__device__ __forceinline__ uint32_t pack_h2(float a, float b) {
    __half2 t = __floats2half2_rn(a, b);
    uint32_t u; memcpy(&u, &t, 4); return u;
}

// ---------------- pure fp16 HMMA GEMM (R9 skeleton) ----------------------------
// C[M,N] = A[M,K] @ B[N,K]^T, fp16 in, fp32 accum. BM=BN=128, BK=64.
// 256 threads = 8 warps, 4(M)x2(N) grid, warp tile 32x64.
// 3-stage cp.async, one barrier/iter. L2-friendly CTA swizzle (G=16).
// MODE 0: Cf = acc + bias
// MODE 2: Cb = fp16(gelu(acc + bias)), row width KOUT
// MODE 3: Cf = acc + bias + res1 + res2
#define STAGE_BYTES 32768       // 16KB A + 16KB B
#define NSTAGE 3
#define RASTER_G 16

template<int MODE>
__global__ void __launch_bounds__(256, 2) mma_gemm(
    int Nn, int Kk,
    const __half* __restrict__ A, const __half* __restrict__ Bw,
    const float* __restrict__ bias,
    const float* __restrict__ res1, const float* __restrict__ res2,
    float* __restrict__ Cf, __half* __restrict__ Cb, int KOUT)
{
    extern __shared__ char smraw[];
    const uint32_t smb = smem_u32(smraw);

    const int tid = threadIdx.x;
    const int numX = gridDim.x, numY = gridDim.y;
    const int bid = blockIdx.y * numX + blockIdx.x;
    const int strip = RASTER_G * numX;
    const int sIdx = bid / strip;
    const int rIdx = bid % strip;
    const int gRows = (numY - sIdx * RASTER_G) < RASTER_G ? (numY - sIdx * RASTER_G)
                                                          : RASTER_G;
    const int by = sIdx * RASTER_G + (rIdx % gRows);
    const int bx = rIdx / gRows;

    const int w = tid >> 5, lane = tid & 31;
    const int m0w = (w & 3) * 32, n0w = (w >> 2) * 64;

    const __half* Abase = A  + (size_t)(by * 128) * Kk;
    const __half* Bbase = Bw + (size_t)(bx * 128) * Kk;
    const int nch = Kk >> 6;

    auto load_stage = [&](int c, int s) {
        const uint32_t sa = smb + s * STAGE_BYTES;
        const uint32_t sb = sa + 16384;
        const int k0 = c * 64;
#pragma unroll
        for (int i = 0; i < 4; i++) {
            int idx = tid + i * 256;
            int row = idx >> 3, cc = idx & 7;
            uint32_t off = row * 128 + ((cc ^ (row & 7)) << 4);
            cp16(sa + off, Abase + (size_t)row * Kk + k0 + cc * 8);
            cp16(sb + off, Bbase + (size_t)row * Kk + k0 + cc * 8);
        }
        asm volatile("cp.async.commit_group;" ::: "memory");
    };

    float acc[2][8][4];
#pragma unroll
    for (int i = 0; i < 2; i++)
#pragma unroll
        for (int j = 0; j < 8; j++)
#pragma unroll
            for (int q = 0; q < 4; q++) acc[i][j][q] = 0.0f;

    const int a_row = m0w + (lane & 15);
    const int a_ccb = lane >> 4;
    const int b_row = n0w + (lane & 7) + ((lane >> 4) << 3);
    const int b_ccb = (lane >> 3) & 1;

    load_stage(0, 0);
    if (nch > 1) load_stage(1, 1);

    for (int c = 0; c < nch; c++) {
        const int s = c % NSTAGE;
        if (c + 1 < nch) asm volatile("cp.async.wait_group 1;" ::: "memory");
        else             asm volatile("cp.async.wait_group 0;" ::: "memory");
        __syncthreads();
        if (c + 2 < nch) load_stage(c + 2, (c + 2) % NSTAGE);

        const uint32_t sa = smb + s * STAGE_BYTES;
        const uint32_t sb = sa + 16384;
#pragma unroll
        for (int kk = 0; kk < 4; kk++) {
            uint32_t af[2][4];
#pragma unroll
            for (int mi = 0; mi < 2; mi++) {
                int row = a_row + mi * 16;
                int cc = kk * 2 + a_ccb;
                ldsm4(af[mi], sa + row * 128 + ((cc ^ (row & 7)) << 4));
            }
#pragma unroll
            for (int nj = 0; nj < 4; nj++) {
                uint32_t bf[4];
                int row = b_row + nj * 16;
                int cc = kk * 2 + b_ccb;
                ldsm4(bf, sb + row * 128 + ((cc ^ (row & 7)) << 4));
#pragma unroll
                for (int mi = 0; mi < 2; mi++) {
                    mma16816(acc[mi][nj * 2],     af[mi], bf[0], bf[1]);
                    mma16816(acc[mi][nj * 2 + 1], af[mi], bf[2], bf[3]);
                }
            }
        }
    }

    const int g = lane >> 2, t = lane & 3;
#pragma unroll
    for (int mi = 0; mi < 2; mi++) {
#pragma unroll
        for (int ni = 0; ni < 8; ni++) {
            const int col = bx * 128 + n0w + ni * 8 + 2 * t;
            const float b0 = __ldg(bias + col);
            const float b1 = __ldg(bias + col + 1);
            const int row0 = by * 128 + m0w + mi * 16 + g;
#pragma unroll
            for (int h = 0; h < 2; h++) {
                const int row = row0 + h * 8;
                float v0 = acc[mi][ni][2 * h]     + b0;
                float v1 = acc[mi][ni][2 * h + 1] + b1;
                if (MODE == 2) {
                    v0 = gelu_exact(v0); v1 = gelu_exact(v1);
                    *(uint32_t*)(Cb + (size_t)row * KOUT + col) = pack_h2(v0, v1);
                } else {
                    const size_t base = (size_t)row * Nn + col;
                    if (MODE == 3) {
                        v0 += res1[base]     + res2[base];
                        v1 += res1[base + 1] + res2[base + 1];
                    }
                    *(float2*)(Cf + base) = make_float2(v0, v1);
                }
            }
        }
    }
}

// ---------------- conversions --------------------------------------------------
// activation: X[M,K] fp32 -> Y[M,K] fp16
__global__ void aconv_kernel(const float* __restrict__ X, __half* __restrict__ Y,
                             size_t n)
{
    size_t i = ((size_t)blockIdx.x * blockDim.x + threadIdx.x) * 4;
    if (i >= n) return;
    float4 v = *(const float4*)(X + i);
    *(uint2*)(Y + i) = make_uint2(pack_h2(v.x, v.y), pack_h2(v.z, v.w));
}

// weight: W[K,N] fp32 -> Y[N,K] fp16 (transpose + convert)
__global__ void wconv_kernel(const float* __restrict__ W, __half* __restrict__ Y,
                             int K, int N)
{
    size_t i = (size_t)blockIdx.x * blockDim.x + threadIdx.x;
    if (i >= (size_t)K * N) return;
    int n = (int)(i / K), k = (int)(i % K);
    Y[(size_t)n * K + k] = __float2half_rn(W[(size_t)k * N + n]);
}

// ---------------- attention: 8 q/warp-iter, fp16 output ------------------------
#define QPB 256
#define KPAD 65

__global__ void __launch_bounds__(256) attn_kernel(
    const float* __restrict__ Q, const float* __restrict__ K,
    const float* __restrict__ V, __half* __restrict__ O)
{
    extern __shared__ float sm[];
    float* Ks = sm;                      // 256*65
    float* Vs = Ks + 256 * KPAD;         // 256*65
    float* qs = Vs + 256 * KPAD;         // 8 warps * 8 q * 64
    float* ps = qs + 8 * 8 * 64;         // 8 warps * 8 q * 256

    const int nchunk = TXQ / QPB;
    const int bid   = blockIdx.x;
    const int chunk = bid % nchunk;
    const int h     = (bid / nchunk) % NHEADS;
    const int b     = bid / (nchunk * NHEADS);

    const int tid  = threadIdx.x;
    const int lane = tid & 31;
    const int w    = tid >> 5;

    for (int i = tid; i < 256 * 16; i += 256) {
        int j  = i >> 4;
        int dq = (i & 15) * 4;
        size_t gbase = (size_t)(b * TXFK + j) * DMODEL + h * HDIM + dq;
        float4 kv = *(const float4*)(K + gbase);
        float4 vv = *(const float4*)(V + gbase);
        Ks[j * KPAD + dq + 0] = kv.x; Ks[j * KPAD + dq + 1] = kv.y;
        Ks[j * KPAD + dq + 2] = kv.z; Ks[j * KPAD + dq + 3] = kv.w;
        Vs[j * KPAD + dq + 0] = vv.x; Vs[j * KPAD + dq + 1] = vv.y;
        Vs[j * KPAD + dq + 2] = vv.z; Vs[j * KPAD + dq + 3] = vv.w;
    }
    __syncthreads();

    float* qw = qs + w * 8 * 64;
    float* pw = ps + w * 8 * 256;

    for (int qt = 0; qt < 4; qt++) {
        const size_t qrow0 = (size_t)b * TXQ + (size_t)chunk * QPB + w * 32 + qt * 8;
#pragma unroll
        for (int r = 0; r < 8; r++) {
            const float* qp = Q + (qrow0 + r) * DMODEL + h * HDIM;
            qw[r * 64 + lane]      = qp[lane];
            qw[r * 64 + lane + 32] = qp[lane + 32];
        }
        __syncwarp();

        float s[8][8];
#pragma unroll
        for (int r = 0; r < 8; r++)
#pragma unroll
            for (int c = 0; c < 8; c++) s[r][c] = 0.0f;

        for (int d = 0; d < 64; d += 2) {
            float ka[8], kb[8];
#pragma unroll
            for (int c = 0; c < 8; c++) {
                ka[c] = Ks[(lane + 32 * c) * KPAD + d];
                kb[c] = Ks[(lane + 32 * c) * KPAD + d + 1];
            }
#pragma unroll
            for (int r = 0; r < 8; r++) {
                float2 q2 = *(const float2*)&qw[r * 64 + d];
#pragma unroll
                for (int c = 0; c < 8; c++)
                    s[r][c] += q2.x * ka[c] + q2.y * kb[c];
            }
        }

#pragma unroll
        for (int r = 0; r < 8; r++) {
#pragma unroll
            for (int c = 0; c < 8; c++) s[r][c] *= ATT_SCALE;
            float mx = s[r][0];
#pragma unroll
            for (int c = 1; c < 8; c++) mx = fmaxf(mx, s[r][c]);
#pragma unroll
            for (int o = 16; o; o >>= 1) mx = fmaxf(mx, __shfl_xor_sync(~0u, mx, o));
            float sum = 0.0f;
#pragma unroll
            for (int c = 0; c < 8; c++) { s[r][c] = __expf(s[r][c] - mx); sum += s[r][c]; }
#pragma unroll
            for (int o = 16; o; o >>= 1) sum += __shfl_xor_sync(~0u, sum, o);
            float inv = 1.0f / sum;
#pragma unroll
            for (int c = 0; c < 8; c++) pw[r * 256 + lane + 32 * c] = s[r][c] * inv;
        }
        __syncwarp();

        float o0[8], o1[8];
#pragma unroll
        for (int r = 0; r < 8; r++) { o0[r] = 0.0f; o1[r] = 0.0f; }
        for (int j = 0; j < 256; j += 2) {
            float va0 = Vs[j * KPAD + lane];
            float va1 = Vs[j * KPAD + lane + 32];
            float vb0 = Vs[(j + 1) * KPAD + lane];
            float vb1 = Vs[(j + 1) * KPAD + lane + 32];
#pragma unroll
            for (int r = 0; r < 8; r++) {
                float2 p2 = *(const float2*)&pw[r * 256 + j];
                o0[r] += p2.x * va0 + p2.y * vb0;
                o1[r] += p2.x * va1 + p2.y * vb1;
            }
        }
#pragma unroll
        for (int r = 0; r < 8; r++) {
            const size_t rb = (qrow0 + r) * (size_t)DMODEL + h * HDIM;
            O[rb + lane]      = __float2half_rn(o0[r]);
            O[rb + lane + 32] = __float2half_rn(o1[r]);
        }
        __syncwarp();
    }
}

// ---------------- LayerNorm -> fp16 --------------------------------------------
__global__ void __launch_bounds__(256) ln_conv_kernel(
    const float* __restrict__ X, const float* __restrict__ gw,
    const float* __restrict__ bw, __half* __restrict__ Y)
{
    const int row = blockIdx.x;
    const int t = threadIdx.x;
    float4 v = ((const float4*)(X + (size_t)row * DMODEL))[t];
    float s1 = v.x + v.y + v.z + v.w;
    float s2 = v.x * v.x + v.y * v.y + v.z * v.z + v.w * v.w;
#pragma unroll
    for (int o = 16; o; o >>= 1) {
        s1 += __shfl_xor_sync(~0u, s1, o);
        s2 += __shfl_xor_sync(~0u, s2, o);
    }
    __shared__ float r1[8], r2[8];
    const int w = t >> 5, lane = t & 31;
    if (lane == 0) { r1[w] = s1; r2[w] = s2; }
    __syncthreads();
    if (w == 0) {
        s1 = (lane < 8) ? r1[lane] : 0.0f;
        s2 = (lane < 8) ? r2[lane] : 0.0f;
#pragma unroll
        for (int o = 4; o; o >>= 1) {
            s1 += __shfl_xor_sync(~0u, s1, o);
            s2 += __shfl_xor_sync(~0u, s2, o);
        }
        if (lane == 0) { r1[0] = s1; r2[0] = s2; }
    }
    __syncthreads();
    const float mean = r1[0] * (1.0f / DMODEL);
    const float var  = r2[0] * (1.0f / DMODEL) - mean * mean;
    const float rstd = rsqrtf(var + 1e-5f);
    float4 g4 = ((const float4*)gw)[t];
    float4 b4 = ((const float4*)bw)[t];
    float vv[4];
    vv[0] = (v.x - mean) * rstd * g4.x + b4.x;
    vv[1] = (v.y - mean) * rstd * g4.y + b4.y;
    vv[2] = (v.z - mean) * rstd * g4.z + b4.z;
    vv[3] = (v.w - mean) * rstd * g4.w + b4.w;

    *(uint2*)(Y + (size_t)row * DMODEL + t * 4) =
        make_uint2(pack_h2(vv[0], vv[1]), pack_h2(vv[2], vv[3]));
}

// ---------------- launch -------------------------------------------------------
extern "C" void kernel_launch(void* const* d_in, const int* in_sizes, int n_in,
                              void* d_out, int out_size)
{
    const float* x    = (const float*)d_in[0];
    const float* xf   = (const float*)d_in[1];
    const float* Wq   = (const float*)d_in[2];
    const float* bq   = (const float*)d_in[3];
    const float* Wk   = (const float*)d_in[4];
    const float* bk   = (const float*)d_in[5];
    const float* Wv   = (const float*)d_in[6];
    const float* bv   = (const float*)d_in[7];
    const float* Wo   = (const float*)d_in[8];
    const float* bo   = (const float*)d_in[9];
    const float* ln_g = (const float*)d_in[10];
    const float* ln_b = (const float*)d_in[11];
    const float* W1   = (const float*)d_in[12];
    const float* b1   = (const float*)d_in[13];
    const float* W2   = (const float*)d_in[14];
    const float* b2   = (const float*)d_in[15];
    float* out = (float*)d_out;

    float *q, *k, *v, *res;
    __half *xs, *xfs, *attns, *lns, *hs, *wq, *wk, *wv, *wo, *w1, *w2;
    cudaGetSymbolAddress((void**)&q,     g_q);
    cudaGetSymbolAddress((void**)&k,     g_k);
    cudaGetSymbolAddress((void**)&v,     g_v);
    cudaGetSymbolAddress((void**)&res,   g_res);
    cudaGetSymbolAddress((void**)&xs,    g_xs);
    cudaGetSymbolAddress((void**)&xfs,   g_xfs);
    cudaGetSymbolAddress((void**)&attns, g_attns);
    cudaGetSymbolAddress((void**)&lns,   g_lns);
    cudaGetSymbolAddress((void**)&hs,    g_hs);
    cudaGetSymbolAddress((void**)&wq,    g_wq);
    cudaGetSymbolAddress((void**)&wk,    g_wk);
    cudaGetSymbolAddress((void**)&wv,    g_wv);
    cudaGetSymbolAddress((void**)&wo,    g_wo);
    cudaGetSymbolAddress((void**)&w1,    g_w1);
    cudaGetSymbolAddress((void**)&w2,    g_w2);

    const int GEMM_SMEM = NSTAGE * STAGE_BYTES;   // 96KB
    cudaFuncSetAttribute(mma_gemm<0>, cudaFuncAttributeMaxDynamicSharedMemorySize, GEMM_SMEM);
    cudaFuncSetAttribute(mma_gemm<2>, cudaFuncAttributeMaxDynamicSharedMemorySize, GEMM_SMEM);
    cudaFuncSetAttribute(mma_gemm<3>, cudaFuncAttributeMaxDynamicSharedMemorySize, GEMM_SMEM);
    const size_t attn_smem =
        (size_t)(2 * 256 * KPAD + 8 * 8 * 64 + 8 * 8 * 256) * sizeof(float);
    cudaFuncSetAttribute(attn_kernel, cudaFuncAttributeMaxDynamicSharedMemorySize,
                         (int)attn_smem);

    dim3 blk(256);
    auto cdiv = [](size_t a, size_t b) { return (unsigned)((a + b - 1) / b); };

    // weight transpose+convert
    wconv_kernel<<<cdiv((size_t)DMODEL * DMODEL, 256), blk>>>(Wq, wq, DMODEL, DMODEL);
    wconv_kernel<<<cdiv((size_t)DTEXT  * DMODEL, 256), blk>>>(Wk, wk, DTEXT,  DMODEL);
    wconv_kernel<<<cdiv((size_t)DTEXT  * DMODEL, 256), blk>>>(Wv, wv, DTEXT,  DMODEL);
    wconv_kernel<<<cdiv((size_t)DMODEL * DMODEL, 256), blk>>>(Wo, wo, DMODEL, DMODEL);
    wconv_kernel<<<cdiv((size_t)DMODEL * DFF,    256), blk>>>(W1, w1, DMODEL, DFF);
    wconv_kernel<<<cdiv((size_t)DFF    * DMODEL, 256), blk>>>(W2, w2, DFF,    DMODEL);
    // activation converts
    aconv_kernel<<<cdiv((size_t)MQ  * DMODEL / 4, 256), blk>>>(x,  xs,  (size_t)MQ  * DMODEL);
    aconv_kernel<<<cdiv((size_t)MKV * DTEXT  / 4, 256), blk>>>(xf, xfs, (size_t)MKV * DTEXT);

    // Q = x@Wq + bq ; K/V = xf@W{k,v} + b
    mma_gemm<0><<<dim3(DMODEL / 128, MQ / 128), blk, GEMM_SMEM>>>(
        DMODEL, DMODEL, xs, wq, bq, nullptr, nullptr, q, nullptr, 0);
    mma_gemm<0><<<dim3(DMODEL / 128, MKV / 128), blk, GEMM_SMEM>>>(
        DMODEL, DTEXT, xfs, wk, bk, nullptr, nullptr, k, nullptr, 0);
    mma_gemm<0><<<dim3(DMODEL / 128, MKV / 128), blk, GEMM_SMEM>>>(
        DMODEL, DTEXT, xfs, wv, bv, nullptr, nullptr, v, nullptr, 0);

    // attention (writes fp16 output directly)
    attn_kernel<<<BDIM * NHEADS * (TXQ / QPB), blk, attn_smem>>>(q, k, v, attns);

    // out = attn@Wo + bo (residual base)
    mma_gemm<0><<<dim3(DMODEL / 128, MQ / 128), blk, GEMM_SMEM>>>(
        DMODEL, DMODEL, attns, wo, bo, nullptr, nullptr, res, nullptr, 0);

    // LayerNorm -> fp16
    ln_conv_kernel<<<MQ, blk>>>(res, ln_g, ln_b, lns);

    // h = GELU(ln@W1 + b1) -> fp16
    mma_gemm<2><<<dim3(DFF / 128, MQ / 128), blk, GEMM_SMEM>>>(
        DFF, DMODEL, lns, w1, b1, nullptr, nullptr, nullptr, hs, DFF);

    // final = h@W2 + b2 + res + x
    mma_gemm<3><<<dim3(DMODEL / 128, MQ / 128), blk, GEMM_SMEM>>>(
        DMODEL, DFF, hs, w2, b2, res, x, out, nullptr, 0);
}

// round 12
// speedup vs baseline: 3.5505x; 1.5624x over previous
#include <cuda_runtime.h>
#include <cuda_fp16.h>
#include <math.h>
#include <stdint.h>

#define BDIM   4
#define TXQ    4096
#define TXFK   256
#define DMODEL 1024
#define DTEXT  768
#define NHEADS 16
#define HDIM   64
#define MQ     (BDIM*TXQ)     // 16384
#define MKV    (BDIM*TXFK)    // 1024
#define DFF    4096
#define ATT_SCALE 0.125f

// ---------------- scratch (device globals) -----------------------------------
__device__ float g_res [(size_t)MQ * DMODEL];

// fp16 buffers
__device__ __half g_xs   [(size_t)MQ  * DMODEL];
__device__ __half g_xfs  [(size_t)MKV * DTEXT];
__device__ __half g_qh   [(size_t)MQ  * DMODEL];
__device__ __half g_kh   [(size_t)MKV * DMODEL];
__device__ __half g_vh   [(size_t)MKV * DMODEL];
__device__ __half g_attns[(size_t)MQ  * DMODEL];
__device__ __half g_lns  [(size_t)MQ  * DMODEL];
__device__ __half g_hs   [(size_t)MQ  * DFF];
__device__ __half g_wq   [(size_t)DMODEL * DMODEL];
__device__ __half g_wk   [(size_t)DMODEL * DTEXT];
__device__ __half g_wv   [(size_t)DMODEL * DTEXT];
__device__ __half g_wo   [(size_t)DMODEL * DMODEL];
__device__ __half g_w1   [(size_t)DFF    * DMODEL];
__device__ __half g_w2   [(size_t)DMODEL * DFF];

__device__ __forceinline__ float gelu_exact(float v) {
    return 0.5f * v * (1.0f + erff(v * 0.7071067811865476f));
}

// ---------------- PTX helpers (target-portable, sm_80+) -----------------------
__device__ __forceinline__ uint32_t smem_u32(const void* p) {
    uint32_t a;
    asm("{ .reg .u64 t; cvta.to.shared.u64 t, %1; cvt.u32.u64 %0, t; }"
        : "=r"(a) : "l"(p));
    return a;
}
__device__ __forceinline__ void cp16(uint32_t s, const void* g) {
    asm volatile("cp.async.cg.shared.global [%0], [%1], 16;" :: "r"(s), "l"(g));
}
__device__ __forceinline__ void ldsm4(uint32_t* r, uint32_t a) {
    asm volatile("ldmatrix.sync.aligned.m8n8.x4.shared.b16 {%0,%1,%2,%3}, [%4];"
        : "=r"(r[0]), "=r"(r[1]), "=r"(r[2]), "=r"(r[3]) : "r"(a));
}
__device__ __forceinline__ void ldsm4t(uint32_t* r, uint32_t a) {
    asm volatile("ldmatrix.sync.aligned.m8n8.x4.trans.shared.b16 {%0,%1,%2,%3}, [%4];"
        : "=r"(r[0]), "=r"(r[1]), "=r"(r[2]), "=r"(r[3]) : "r"(a));
}
__device__ __forceinline__ void mma16816(float* c, const uint32_t* a,
                                         uint32_t b0, uint32_t b1) {
    asm volatile(
        "mma.sync.aligned.m16n8k16.row.col.f32.f16.f16.f32 "
        "{%0,%1,%2,%3}, {%4,%5,%6,%7}, {%8,%9}, {%0,%1,%2,%3};"
        : "+f"(c[0]), "+f"(c[1]), "+f"(c[2]), "+f"(c[3])
        : "r"(a[0]), "r"(a[1]), "r"(a[2]), "r"(a[3]), "r"(b0), "r"(b1));
}
__device__ __forceinline__ uint32_t pack_h2(float a, float b) {
    __half2 t = __floats2half2_rn(a, b);
    uint32_t u; memcpy(&u, &t, 4); return u;
}
// fast exp on FMA pipe (avoids MUFU bottleneck). rel err ~2e-6 for x <= 0.
__device__ __forceinline__ float fexp(float x) {
    x = fmaxf(x, -60.0f);
    float y = x * 1.4426950408889634f;
    float r = rintf(y);
    float f = y - r;
    float p =          1.3333558e-3f;
    p = fmaf(p, f,     9.6181291e-3f);
    p = fmaf(p, f,     5.5504109e-2f);
    p = fmaf(p, f,     2.4022651e-1f);
    p = fmaf(p, f,     6.9314718e-1f);
    p = fmaf(p, f,     1.0f);
    return __int_as_float(__float_as_int(p) + (((int)r) << 23));
}

// ---------------- pure fp16 HMMA GEMM ------------------------------------------
// C[M,N] = A[M,K] @ B[N,K]^T, fp16 in, fp32 accum. BM=BN=128, BK=64.
// MODE 0: Cf = acc + bias
// MODE 2: Cb = fp16(gelu(acc + bias))
// MODE 3: Cf = acc + bias + res1 + res2
// MODE 4: Cb = fp16(acc + bias)
#define STAGE_BYTES 32768
#define NSTAGE 3
#define RASTER_G 16

template<int MODE>
__global__ void __launch_bounds__(256, 2) mma_gemm(
    int Nn, int Kk,
    const __half* __restrict__ A, const __half* __restrict__ Bw,
    const float* __restrict__ bias,
    const float* __restrict__ res1, const float* __restrict__ res2,
    float* __restrict__ Cf, __half* __restrict__ Cb, int KOUT)
{
    extern __shared__ char smraw[];
    const uint32_t smb = smem_u32(smraw);

    const int tid = threadIdx.x;
    const int numX = gridDim.x, numY = gridDim.y;
    const int bid = blockIdx.y * numX + blockIdx.x;
    const int strip = RASTER_G * numX;
    const int sIdx = bid / strip;
    const int rIdx = bid % strip;
    const int gRows = (numY - sIdx * RASTER_G) < RASTER_G ? (numY - sIdx * RASTER_G)
                                                          : RASTER_G;
    const int by = sIdx * RASTER_G + (rIdx % gRows);
    const int bx = rIdx / gRows;

    const int w = tid >> 5, lane = tid & 31;
    const int m0w = (w & 3) * 32, n0w = (w >> 2) * 64;

    const __half* Abase = A  + (size_t)(by * 128) * Kk;
    const __half* Bbase = Bw + (size_t)(bx * 128) * Kk;
    const int nch = Kk >> 6;

    auto load_stage = [&](int c, int s) {
        const uint32_t sa = smb + s * STAGE_BYTES;
        const uint32_t sb = sa + 16384;
        const int k0 = c * 64;
#pragma unroll
        for (int i = 0; i < 4; i++) {
            int idx = tid + i * 256;
            int row = idx >> 3, cc = idx & 7;
            uint32_t off = row * 128 + ((cc ^ (row & 7)) << 4);
            cp16(sa + off, Abase + (size_t)row * Kk + k0 + cc * 8);
            cp16(sb + off, Bbase + (size_t)row * Kk + k0 + cc * 8);
        }
        asm volatile("cp.async.commit_group;" ::: "memory");
    };

    float acc[2][8][4];
#pragma unroll
    for (int i = 0; i < 2; i++)
#pragma unroll
        for (int j = 0; j < 8; j++)
#pragma unroll
            for (int q = 0; q < 4; q++) acc[i][j][q] = 0.0f;

    const int a_row = m0w + (lane & 15);
    const int a_ccb = lane >> 4;
    const int b_row = n0w + (lane & 7) + ((lane >> 4) << 3);
    const int b_ccb = (lane >> 3) & 1;

    load_stage(0, 0);
    if (nch > 1) load_stage(1, 1);

    for (int c = 0; c < nch; c++) {
        const int s = c % NSTAGE;
        if (c + 1 < nch) asm volatile("cp.async.wait_group 1;" ::: "memory");
        else             asm volatile("cp.async.wait_group 0;" ::: "memory");
        __syncthreads();
        if (c + 2 < nch) load_stage(c + 2, (c + 2) % NSTAGE);

        const uint32_t sa = smb + s * STAGE_BYTES;
        const uint32_t sb = sa + 16384;
#pragma unroll
        for (int kk = 0; kk < 4; kk++) {
            uint32_t af[2][4];
#pragma unroll
            for (int mi = 0; mi < 2; mi++) {
                int row = a_row + mi * 16;
                int cc = kk * 2 + a_ccb;
                ldsm4(af[mi], sa + row * 128 + ((cc ^ (row & 7)) << 4));
            }
#pragma unroll
            for (int nj = 0; nj < 4; nj++) {
                uint32_t bf[4];
                int row = b_row + nj * 16;
                int cc = kk * 2 + b_ccb;
                ldsm4(bf, sb + row * 128 + ((cc ^ (row & 7)) << 4));
#pragma unroll
                for (int mi = 0; mi < 2; mi++) {
                    mma16816(acc[mi][nj * 2],     af[mi], bf[0], bf[1]);
                    mma16816(acc[mi][nj * 2 + 1], af[mi], bf[2], bf[3]);
                }
            }
        }
    }

    const int g = lane >> 2, t = lane & 3;
#pragma unroll
    for (int mi = 0; mi < 2; mi++) {
#pragma unroll
        for (int ni = 0; ni < 8; ni++) {
            const int col = bx * 128 + n0w + ni * 8 + 2 * t;
            const float b0 = __ldg(bias + col);
            const float b1 = __ldg(bias + col + 1);
            const int row0 = by * 128 + m0w + mi * 16 + g;
#pragma unroll
            for (int h = 0; h < 2; h++) {
                const int row = row0 + h * 8;
                float v0 = acc[mi][ni][2 * h]     + b0;
                float v1 = acc[mi][ni][2 * h + 1] + b1;
                if (MODE == 2) {
                    v0 = gelu_exact(v0); v1 = gelu_exact(v1);
                    *(uint32_t*)(Cb + (size_t)row * KOUT + col) = pack_h2(v0, v1);
                } else if (MODE == 4) {
                    *(uint32_t*)(Cb + (size_t)row * KOUT + col) = pack_h2(v0, v1);
                } else {
                    const size_t base = (size_t)row * Nn + col;
                    if (MODE == 3) {
                        v0 += res1[base]     + res2[base];
                        v1 += res1[base + 1] + res2[base + 1];
                    }
                    *(float2*)(Cf + base) = make_float2(v0, v1);
                }
            }
        }
    }
}

// ---------------- conversions --------------------------------------------------
__global__ void aconv_kernel(const float* __restrict__ X, __half* __restrict__ Y,
                             size_t n)
{
    size_t i = ((size_t)blockIdx.x * blockDim.x + threadIdx.x) * 4;
    if (i >= n) return;
    float4 v = *(const float4*)(X + i);
    *(uint2*)(Y + i) = make_uint2(pack_h2(v.x, v.y), pack_h2(v.z, v.w));
}

__global__ void wconv_kernel(const float* __restrict__ W, __half* __restrict__ Y,
                             int K, int N)
{
    size_t i = (size_t)blockIdx.x * blockDim.x + threadIdx.x;
    if (i >= (size_t)K * N) return;
    int n = (int)(i / K), k = (int)(i % K);
    Y[(size_t)n * K + k] = __float2half_rn(W[(size_t)k * N + n]);
}

// ---------------- HMMA flash-attention -----------------------------------------
// One CTA = 128 q rows x one (b,h). 8 warps, warp = 16 q rows.
// Online softmax over 4 key chunks of 64. fp16 in/out, fp32 accum.
#define AQT 128

__global__ void __launch_bounds__(256, 2) attn_kernel(
    const __half* __restrict__ Qh, const __half* __restrict__ Kh,
    const __half* __restrict__ Vh, __half* __restrict__ O)
{
    extern __shared__ char smraw[];
    const uint32_t smb = smem_u32(smraw);
    const uint32_t sQ = smb;             // 128 x 128B = 16KB
    const uint32_t sK = smb + 16384;     // 256 x 128B = 32KB
    const uint32_t sV = smb + 49152;     // 256 x 128B = 32KB

    const int bid   = blockIdx.x;
    const int chunk = bid & 31;
    const int h     = (bid >> 5) & 15;
    const int b     = bid >> 9;

    const int tid  = threadIdx.x;
    const int lane = tid & 31;
    const int w    = tid >> 5;

    {
        const __half* qg = Qh + (size_t)(b * TXQ + chunk * AQT) * DMODEL + h * HDIM;
        const __half* kg = Kh + (size_t)(b * TXFK) * DMODEL + h * HDIM;
        const __half* vg = Vh + (size_t)(b * TXFK) * DMODEL + h * HDIM;
#pragma unroll
        for (int i = 0; i < 4; i++) {
            int idx = tid + i * 256;
            int row = idx >> 3, cc = idx & 7;
            uint32_t off = row * 128 + ((cc ^ (row & 7)) << 4);
            cp16(sQ + off, qg + (size_t)row * DMODEL + cc * 8);
        }
#pragma unroll
        for (int i = 0; i < 8; i++) {
            int idx = tid + i * 256;
            int row = idx >> 3, cc = idx & 7;
            uint32_t off = row * 128 + ((cc ^ (row & 7)) << 4);
            cp16(sK + off, kg + (size_t)row * DMODEL + cc * 8);
            cp16(sV + off, vg + (size_t)row * DMODEL + cc * 8);
        }
        asm volatile("cp.async.commit_group;" ::: "memory");
        asm volatile("cp.async.wait_group 0;" ::: "memory");
        __syncthreads();
    }

    // Q fragments: warp's 16 rows, 4 k-steps over 64 dims
    uint32_t qf[4][4];
#pragma unroll
    for (int s = 0; s < 4; s++) {
        int row = w * 16 + (lane & 15);
        int cc = 2 * s + (lane >> 4);
        ldsm4(qf[s], sQ + row * 128 + ((cc ^ (row & 7)) << 4));
    }

    float oacc[8][4];
#pragma unroll
    for (int j = 0; j < 8; j++)
#pragma unroll
        for (int q = 0; q < 4; q++) oacc[j][q] = 0.0f;
    float m0 = -1e30f, m1 = -1e30f, l0 = 0.0f, l1 = 0.0f;

    for (int c = 0; c < 4; c++) {
        const int kb = c * 64;
        float sacc[8][4];
#pragma unroll
        for (int j = 0; j < 8; j++)
#pragma unroll
            for (int q = 0; q < 4; q++) sacc[j][q] = 0.0f;

        // S = Q @ K^T for this key chunk
#pragma unroll
        for (int s = 0; s < 4; s++) {
#pragma unroll
            for (int njp = 0; njp < 4; njp++) {
                uint32_t kf[4];
                int row = kb + njp * 16 + (lane & 7) + ((lane >> 4) << 3);
                int cc = 2 * s + ((lane >> 3) & 1);
                ldsm4(kf, sK + row * 128 + ((cc ^ (row & 7)) << 4));
                mma16816(sacc[njp * 2],     qf[s], kf[0], kf[1]);
                mma16816(sacc[njp * 2 + 1], qf[s], kf[2], kf[3]);
            }
        }

        // online softmax (rows g and g+8; cols spread over quad lanes t=0..3)
        float mx0 = -1e30f, mx1 = -1e30f;
#pragma unroll
        for (int j = 0; j < 8; j++) {
            sacc[j][0] *= ATT_SCALE; sacc[j][1] *= ATT_SCALE;
            sacc[j][2] *= ATT_SCALE; sacc[j][3] *= ATT_SCALE;
            mx0 = fmaxf(mx0, fmaxf(sacc[j][0], sacc[j][1]));
            mx1 = fmaxf(mx1, fmaxf(sacc[j][2], sacc[j][3]));
        }
        mx0 = fmaxf(mx0, __shfl_xor_sync(~0u, mx0, 1));
        mx0 = fmaxf(mx0, __shfl_xor_sync(~0u, mx0, 2));
        mx1 = fmaxf(mx1, __shfl_xor_sync(~0u, mx1, 1));
        mx1 = fmaxf(mx1, __shfl_xor_sync(~0u, mx1, 2));
        float m0n = fmaxf(m0, mx0), m1n = fmaxf(m1, mx1);
        float sc0 = fexp(m0 - m0n), sc1 = fexp(m1 - m1n);
        m0 = m0n; m1 = m1n;

        float rs0 = 0.0f, rs1 = 0.0f;
#pragma unroll
        for (int j = 0; j < 8; j++) {
            sacc[j][0] = fexp(sacc[j][0] - m0);
            sacc[j][1] = fexp(sacc[j][1] - m0);
            sacc[j][2] = fexp(sacc[j][2] - m1);
            sacc[j][3] = fexp(sacc[j][3] - m1);
            rs0 += sacc[j][0] + sacc[j][1];
            rs1 += sacc[j][2] + sacc[j][3];
        }
        rs0 += __shfl_xor_sync(~0u, rs0, 1);
        rs0 += __shfl_xor_sync(~0u, rs0, 2);
        rs1 += __shfl_xor_sync(~0u, rs1, 1);
        rs1 += __shfl_xor_sync(~0u, rs1, 2);
        l0 = l0 * sc0 + rs0;
        l1 = l1 * sc1 + rs1;
#pragma unroll
        for (int j = 0; j < 8; j++) {
            oacc[j][0] *= sc0; oacc[j][1] *= sc0;
            oacc[j][2] *= sc1; oacc[j][3] *= sc1;
        }

        // O += P @ V  (P fragments re-packed from S accumulators)
#pragma unroll
        for (int t2 = 0; t2 < 4; t2++) {
            uint32_t pf[4];
            pf[0] = pack_h2(sacc[2 * t2][0],     sacc[2 * t2][1]);
            pf[1] = pack_h2(sacc[2 * t2][2],     sacc[2 * t2][3]);
            pf[2] = pack_h2(sacc[2 * t2 + 1][0], sacc[2 * t2 + 1][1]);
            pf[3] = pack_h2(sacc[2 * t2 + 1][2], sacc[2 * t2 + 1][3]);
            const int kk = kb + t2 * 16;
#pragma unroll
            for (int ndp = 0; ndp < 4; ndp++) {
                uint32_t vf[4];
                int row = kk + ((lane >> 3) & 1) * 8 + (lane & 7);
                int cc = 2 * ndp + (lane >> 4);
                ldsm4t(vf, sV + row * 128 + ((cc ^ (row & 7)) << 4));
                mma16816(oacc[ndp * 2],     pf, vf[0], vf[1]);
                mma16816(oacc[ndp * 2 + 1], pf, vf[2], vf[3]);
            }
        }
    }

    const float inv0 = 1.0f / l0, inv1 = 1.0f / l1;
    const int g = lane >> 2, t = lane & 3;
    const size_t row0 = (size_t)(b * TXQ + chunk * AQT + w * 16 + g);
#pragma unroll
    for (int j = 0; j < 8; j++) {
        int col = h * HDIM + j * 8 + 2 * t;
        *(uint32_t*)(O + row0 * DMODEL + col) =
            pack_h2(oacc[j][0] * inv0, oacc[j][1] * inv0);
        *(uint32_t*)(O + (row0 + 8) * DMODEL + col) =
            pack_h2(oacc[j][2] * inv1, oacc[j][3] * inv1);
    }
}

// ---------------- LayerNorm -> fp16 --------------------------------------------
__global__ void __launch_bounds__(256) ln_conv_kernel(
    const float* __restrict__ X, const float* __restrict__ gw,
    const float* __restrict__ bw, __half* __restrict__ Y)
{
    const int row = blockIdx.x;
    const int t = threadIdx.x;
    float4 v = ((const float4*)(X + (size_t)row * DMODEL))[t];
    float s1 = v.x + v.y + v.z + v.w;
    float s2 = v.x * v.x + v.y * v.y + v.z * v.z + v.w * v.w;
#pragma unroll
    for (int o = 16; o; o >>= 1) {
        s1 += __shfl_xor_sync(~0u, s1, o);
        s2 += __shfl_xor_sync(~0u, s2, o);
    }
    __shared__ float r1[8], r2[8];
    const int w = t >> 5, lane = t & 31;
    if (lane == 0) { r1[w] = s1; r2[w] = s2; }
    __syncthreads();
    if (w == 0) {
        s1 = (lane < 8) ? r1[lane] : 0.0f;
        s2 = (lane < 8) ? r2[lane] : 0.0f;
#pragma unroll
        for (int o = 4; o; o >>= 1) {
            s1 += __shfl_xor_sync(~0u, s1, o);
            s2 += __shfl_xor_sync(~0u, s2, o);
        }
        if (lane == 0) { r1[0] = s1; r2[0] = s2; }
    }
    __syncthreads();
    const float mean = r1[0] * (1.0f / DMODEL);
    const float var  = r2[0] * (1.0f / DMODEL) - mean * mean;
    const float rstd = rsqrtf(var + 1e-5f);
    float4 g4 = ((const float4*)gw)[t];
    float4 b4 = ((const float4*)bw)[t];
    float vv[4];
    vv[0] = (v.x - mean) * rstd * g4.x + b4.x;
    vv[1] = (v.y - mean) * rstd * g4.y + b4.y;
    vv[2] = (v.z - mean) * rstd * g4.z + b4.z;
    vv[3] = (v.w - mean) * rstd * g4.w + b4.w;

    *(uint2*)(Y + (size_t)row * DMODEL + t * 4) =
        make_uint2(pack_h2(vv[0], vv[1]), pack_h2(vv[2], vv[3]));
}

// ---------------- launch -------------------------------------------------------
extern "C" void kernel_launch(void* const* d_in, const int* in_sizes, int n_in,
                              void* d_out, int out_size)
{
    const float* x    = (const float*)d_in[0];
    const float* xf   = (const float*)d_in[1];
    const float* Wq   = (const float*)d_in[2];
    const float* bq   = (const float*)d_in[3];
    const float* Wk   = (const float*)d_in[4];
    const float* bk   = (const float*)d_in[5];
    const float* Wv   = (const float*)d_in[6];
    const float* bv   = (const float*)d_in[7];
    const float* Wo   = (const float*)d_in[8];
    const float* bo   = (const float*)d_in[9];
    const float* ln_g = (const float*)d_in[10];
    const float* ln_b = (const float*)d_in[11];
    const float* W1   = (const float*)d_in[12];
    const float* b1   = (const float*)d_in[13];
    const float* W2   = (const float*)d_in[14];
    const float* b2   = (const float*)d_in[15];
    float* out = (float*)d_out;

    float *res;
    __half *xs, *xfs, *qh, *kh, *vh, *attns, *lns, *hs, *wq, *wk, *wv, *wo, *w1, *w2;
    cudaGetSymbolAddress((void**)&res,   g_res);
    cudaGetSymbolAddress((void**)&xs,    g_xs);
    cudaGetSymbolAddress((void**)&xfs,   g_xfs);
    cudaGetSymbolAddress((void**)&qh,    g_qh);
    cudaGetSymbolAddress((void**)&kh,    g_kh);
    cudaGetSymbolAddress((void**)&vh,    g_vh);
    cudaGetSymbolAddress((void**)&attns, g_attns);
    cudaGetSymbolAddress((void**)&lns,   g_lns);
    cudaGetSymbolAddress((void**)&hs,    g_hs);
    cudaGetSymbolAddress((void**)&wq,    g_wq);
    cudaGetSymbolAddress((void**)&wk,    g_wk);
    cudaGetSymbolAddress((void**)&wv,    g_wv);
    cudaGetSymbolAddress((void**)&wo,    g_wo);
    cudaGetSymbolAddress((void**)&w1,    g_w1);
    cudaGetSymbolAddress((void**)&w2,    g_w2);

    const int GEMM_SMEM = NSTAGE * STAGE_BYTES;   // 96KB
    cudaFuncSetAttribute(mma_gemm<0>, cudaFuncAttributeMaxDynamicSharedMemorySize, GEMM_SMEM);
    cudaFuncSetAttribute(mma_gemm<2>, cudaFuncAttributeMaxDynamicSharedMemorySize, GEMM_SMEM);
    cudaFuncSetAttribute(mma_gemm<3>, cudaFuncAttributeMaxDynamicSharedMemorySize, GEMM_SMEM);
    cudaFuncSetAttribute(mma_gemm<4>, cudaFuncAttributeMaxDynamicSharedMemorySize, GEMM_SMEM);
    const int ATTN_SMEM = 81920;                  // 16KB Q + 32KB K + 32KB V
    cudaFuncSetAttribute(attn_kernel, cudaFuncAttributeMaxDynamicSharedMemorySize, ATTN_SMEM);

    dim3 blk(256);
    auto cdiv = [](size_t a, size_t b) { return (unsigned)((a + b - 1) / b); };

    // weight transpose+convert
    wconv_kernel<<<cdiv((size_t)DMODEL * DMODEL, 256), blk>>>(Wq, wq, DMODEL, DMODEL);
    wconv_kernel<<<cdiv((size_t)DTEXT  * DMODEL, 256), blk>>>(Wk, wk, DTEXT,  DMODEL);
    wconv_kernel<<<cdiv((size_t)DTEXT  * DMODEL, 256), blk>>>(Wv, wv, DTEXT,  DMODEL);
    wconv_kernel<<<cdiv((size_t)DMODEL * DMODEL, 256), blk>>>(Wo, wo, DMODEL, DMODEL);
    wconv_kernel<<<cdiv((size_t)DMODEL * DFF,    256), blk>>>(W1, w1, DMODEL, DFF);
    wconv_kernel<<<cdiv((size_t)DFF    * DMODEL, 256), blk>>>(W2, w2, DFF,    DMODEL);
    // activation converts
    aconv_kernel<<<cdiv((size_t)MQ  * DMODEL / 4, 256), blk>>>(x,  xs,  (size_t)MQ  * DMODEL);
    aconv_kernel<<<cdiv((size_t)MKV * DTEXT  / 4, 256), blk>>>(xf, xfs, (size_t)MKV * DTEXT);

    // Q/K/V projections -> fp16 directly
    mma_gemm<4><<<dim3(DMODEL / 128, MQ / 128), blk, GEMM_SMEM>>>(
        DMODEL, DMODEL, xs, wq, bq, nullptr, nullptr, nullptr, qh, DMODEL);
    mma_gemm<4><<<dim3(DMODEL / 128, MKV / 128), blk, GEMM_SMEM>>>(
        DMODEL, DTEXT, xfs, wk, bk, nullptr, nullptr, nullptr, kh, DMODEL);
    mma_gemm<4><<<dim3(DMODEL / 128, MKV / 128), blk, GEMM_SMEM>>>(
        DMODEL, DTEXT, xfs, wv, bv, nullptr, nullptr, nullptr, vh, DMODEL);

    // HMMA flash-attention -> fp16
    attn_kernel<<<BDIM * NHEADS * (TXQ / AQT), blk, ATTN_SMEM>>>(qh, kh, vh, attns);

    // out = attn@Wo + bo (residual base, fp32)
    mma_gemm<0><<<dim3(DMODEL / 128, MQ / 128), blk, GEMM_SMEM>>>(
        DMODEL, DMODEL, attns, wo, bo, nullptr, nullptr, res, nullptr, 0);

    // LayerNorm -> fp16
    ln_conv_kernel<<<MQ, blk>>>(res, ln_g, ln_b, lns);

    // h = GELU(ln@W1 + b1) -> fp16
    mma_gemm<2><<<dim3(DFF / 128, MQ / 128), blk, GEMM_SMEM>>>(
        DFF, DMODEL, lns, w1, b1, nullptr, nullptr, nullptr, hs, DFF);

    // final = h@W2 + b2 + res + x
    mma_gemm<3><<<dim3(DMODEL / 128, MQ / 128), blk, GEMM_SMEM>>>(
        DMODEL, DFF, hs, w2, b2, res, x, out, nullptr, 0);
}

// round 13
// speedup vs baseline: 3.7117x; 1.0454x over previous
#include <cuda_runtime.h>
#include <cuda_fp16.h>
#include <math.h>
#include <stdint.h>

#define BDIM   4
#define TXQ    4096
#define TXFK   256
#define DMODEL 1024
#define DTEXT  768
#define NHEADS 16
#define HDIM   64
#define MQ     (BDIM*TXQ)     // 16384
#define MKV    (BDIM*TXFK)    // 1024
#define DFF    4096
#define ATT_SCALE 0.125f

// ---------------- scratch (device globals) -----------------------------------
__device__ float g_res [(size_t)MQ * DMODEL];
__device__ float g_bkv [2 * DMODEL];

// fp16 buffers
__device__ __half g_xs   [(size_t)MQ  * DMODEL];
__device__ __half g_xfs  [(size_t)MKV * DTEXT];
__device__ __half g_qh   [(size_t)MQ  * DMODEL];
__device__ __half g_kvh  [(size_t)MKV * 2 * DMODEL];   // [K | V] fused, row 2048
__device__ __half g_attns[(size_t)MQ  * DMODEL];
__device__ __half g_lns  [(size_t)MQ  * DMODEL];
__device__ __half g_hs   [(size_t)MQ  * DFF];
__device__ __half g_wq   [(size_t)DMODEL * DMODEL];
__device__ __half g_wkv  [(size_t)2 * DMODEL * DTEXT]; // rows 0..1023 Wk^T, 1024.. Wv^T
__device__ __half g_wo   [(size_t)DMODEL * DMODEL];
__device__ __half g_w1   [(size_t)DFF    * DMODEL];
__device__ __half g_w2   [(size_t)DMODEL * DFF];

__device__ __forceinline__ float gelu_exact(float v) {
    return 0.5f * v * (1.0f + erff(v * 0.7071067811865476f));
}

// ---------------- PTX helpers (target-portable, sm_80+) -----------------------
__device__ __forceinline__ uint32_t smem_u32(const void* p) {
    uint32_t a;
    asm("{ .reg .u64 t; cvta.to.shared.u64 t, %1; cvt.u32.u64 %0, t; }"
        : "=r"(a) : "l"(p));
    return a;
}
__device__ __forceinline__ void cp16(uint32_t s, const void* g) {
    asm volatile("cp.async.cg.shared.global [%0], [%1], 16;" :: "r"(s), "l"(g));
}
__device__ __forceinline__ void ldsm4(uint32_t* r, uint32_t a) {
    asm volatile("ldmatrix.sync.aligned.m8n8.x4.shared.b16 {%0,%1,%2,%3}, [%4];"
        : "=r"(r[0]), "=r"(r[1]), "=r"(r[2]), "=r"(r[3]) : "r"(a));
}
__device__ __forceinline__ void ldsm4t(uint32_t* r, uint32_t a) {
    asm volatile("ldmatrix.sync.aligned.m8n8.x4.trans.shared.b16 {%0,%1,%2,%3}, [%4];"
        : "=r"(r[0]), "=r"(r[1]), "=r"(r[2]), "=r"(r[3]) : "r"(a));
}
__device__ __forceinline__ void mma16816(float* c, const uint32_t* a,
                                         uint32_t b0, uint32_t b1) {
    asm volatile(
        "mma.sync.aligned.m16n8k16.row.col.f32.f16.f16.f32 "
        "{%0,%1,%2,%3}, {%4,%5,%6,%7}, {%8,%9}, {%0,%1,%2,%3};"
        : "+f"(c[0]), "+f"(c[1]), "+f"(c[2]), "+f"(c[3])
        : "r"(a[0]), "r"(a[1]), "r"(a[2]), "r"(a[3]), "r"(b0), "r"(b1));
}
__device__ __forceinline__ uint32_t pack_h2(float a, float b) {
    __half2 t = __floats2half2_rn(a, b);
    uint32_t u; memcpy(&u, &t, 4); return u;
}
// fast exp on FMA pipe. rel err ~2e-6 for x <= 0.
__device__ __forceinline__ float fexp(float x) {
    x = fmaxf(x, -60.0f);
    float y = x * 1.4426950408889634f;
    float r = rintf(y);
    float f = y - r;
    float p =          1.3333558e-3f;
    p = fmaf(p, f,     9.6181291e-3f);
    p = fmaf(p, f,     5.5504109e-2f);
    p = fmaf(p, f,     2.4022651e-1f);
    p = fmaf(p, f,     6.9314718e-1f);
    p = fmaf(p, f,     1.0f);
    return __int_as_float(__float_as_int(p) + (((int)r) << 23));
}

// ---------------- pure fp16 HMMA GEMM ------------------------------------------
// C[M,N] = A[M,K] @ B[N,K]^T, fp16 in, fp32 accum. BM=BN=128, BK=64.
// MODE 0: Cf = acc + bias
// MODE 2: Cb = fp16(gelu(acc + bias))
// MODE 3: Cf = acc + bias + res1 + res2
// MODE 4: Cb = fp16(acc + bias)
#define STAGE_BYTES 32768
#define NSTAGE 3
#define RASTER_G 16

template<int MODE>
__global__ void __launch_bounds__(256, 2) mma_gemm(
    int Nn, int Kk,
    const __half* __restrict__ A, const __half* __restrict__ Bw,
    const float* __restrict__ bias,
    const float* __restrict__ res1, const float* __restrict__ res2,
    float* __restrict__ Cf, __half* __restrict__ Cb, int KOUT)
{
    extern __shared__ char smraw[];
    const uint32_t smb = smem_u32(smraw);

    const int tid = threadIdx.x;
    const int numX = gridDim.x, numY = gridDim.y;
    const int bid = blockIdx.y * numX + blockIdx.x;
    const int strip = RASTER_G * numX;
    const int sIdx = bid / strip;
    const int rIdx = bid % strip;
    const int gRows = (numY - sIdx * RASTER_G) < RASTER_G ? (numY - sIdx * RASTER_G)
                                                          : RASTER_G;
    const int by = sIdx * RASTER_G + (rIdx % gRows);
    const int bx = rIdx / gRows;

    const int w = tid >> 5, lane = tid & 31;
    const int m0w = (w & 3) * 32, n0w = (w >> 2) * 64;

    const __half* Abase = A  + (size_t)(by * 128) * Kk;
    const __half* Bbase = Bw + (size_t)(bx * 128) * Kk;
    const int nch = Kk >> 6;

    auto load_stage = [&](int c, int s) {
        const uint32_t sa = smb + s * STAGE_BYTES;
        const uint32_t sb = sa + 16384;
        const int k0 = c * 64;
#pragma unroll
        for (int i = 0; i < 4; i++) {
            int idx = tid + i * 256;
            int row = idx >> 3, cc = idx & 7;
            uint32_t off = row * 128 + ((cc ^ (row & 7)) << 4);
            cp16(sa + off, Abase + (size_t)row * Kk + k0 + cc * 8);
            cp16(sb + off, Bbase + (size_t)row * Kk + k0 + cc * 8);
        }
        asm volatile("cp.async.commit_group;" ::: "memory");
    };

    float acc[2][8][4];
#pragma unroll
    for (int i = 0; i < 2; i++)
#pragma unroll
        for (int j = 0; j < 8; j++)
#pragma unroll
            for (int q = 0; q < 4; q++) acc[i][j][q] = 0.0f;

    const int a_row = m0w + (lane & 15);
    const int a_ccb = lane >> 4;
    const int b_row = n0w + (lane & 7) + ((lane >> 4) << 3);
    const int b_ccb = (lane >> 3) & 1;

    load_stage(0, 0);
    if (nch > 1) load_stage(1, 1);

    for (int c = 0; c < nch; c++) {
        const int s = c % NSTAGE;
        if (c + 1 < nch) asm volatile("cp.async.wait_group 1;" ::: "memory");
        else             asm volatile("cp.async.wait_group 0;" ::: "memory");
        __syncthreads();
        if (c + 2 < nch) load_stage(c + 2, (c + 2) % NSTAGE);

        const uint32_t sa = smb + s * STAGE_BYTES;
        const uint32_t sb = sa + 16384;
#pragma unroll
        for (int kk = 0; kk < 4; kk++) {
            uint32_t af[2][4];
#pragma unroll
            for (int mi = 0; mi < 2; mi++) {
                int row = a_row + mi * 16;
                int cc = kk * 2 + a_ccb;
                ldsm4(af[mi], sa + row * 128 + ((cc ^ (row & 7)) << 4));
            }
#pragma unroll
            for (int nj = 0; nj < 4; nj++) {
                uint32_t bf[4];
                int row = b_row + nj * 16;
                int cc = kk * 2 + b_ccb;
                ldsm4(bf, sb + row * 128 + ((cc ^ (row & 7)) << 4));
#pragma unroll
                for (int mi = 0; mi < 2; mi++) {
                    mma16816(acc[mi][nj * 2],     af[mi], bf[0], bf[1]);
                    mma16816(acc[mi][nj * 2 + 1], af[mi], bf[2], bf[3]);
                }
            }
        }
    }

    const int g = lane >> 2, t = lane & 3;
#pragma unroll
    for (int mi = 0; mi < 2; mi++) {
#pragma unroll
        for (int ni = 0; ni < 8; ni++) {
            const int col = bx * 128 + n0w + ni * 8 + 2 * t;
            const float b0 = __ldg(bias + col);
            const float b1 = __ldg(bias + col + 1);
            const int row0 = by * 128 + m0w + mi * 16 + g;
#pragma unroll
            for (int h = 0; h < 2; h++) {
                const int row = row0 + h * 8;
                float v0 = acc[mi][ni][2 * h]     + b0;
                float v1 = acc[mi][ni][2 * h + 1] + b1;
                if (MODE == 2) {
                    v0 = gelu_exact(v0); v1 = gelu_exact(v1);
                    *(uint32_t*)(Cb + (size_t)row * KOUT + col) = pack_h2(v0, v1);
                } else if (MODE == 4) {
                    *(uint32_t*)(Cb + (size_t)row * KOUT + col) = pack_h2(v0, v1);
                } else {
                    const size_t base = (size_t)row * Nn + col;
                    if (MODE == 3) {
                        v0 += res1[base]     + res2[base];
                        v1 += res1[base + 1] + res2[base + 1];
                    }
                    *(float2*)(Cf + base) = make_float2(v0, v1);
                }
            }
        }
    }
}

// ---------------- conversions --------------------------------------------------
__global__ void aconv_kernel(const float* __restrict__ X, __half* __restrict__ Y,
                             size_t n)
{
    size_t i = ((size_t)blockIdx.x * blockDim.x + threadIdx.x) * 4;
    if (i >= n) return;
    float4 v = *(const float4*)(X + i);
    *(uint2*)(Y + i) = make_uint2(pack_h2(v.x, v.y), pack_h2(v.z, v.w));
}

// tiled transpose+convert: W[K,N] fp32 -> Y[(rowOff+n), k] fp16 (row width K)
// grid (N/32, K/32), block (32, 8). Coalesced reads and writes.
__global__ void wtrans_kernel(const float* __restrict__ W, __half* __restrict__ Y,
                              int K, int N, int rowOff)
{
    __shared__ float tile[32][33];
    const int n0 = blockIdx.x * 32, k0 = blockIdx.y * 32;
    const int tx = threadIdx.x, ty = threadIdx.y;
#pragma unroll
    for (int j = 0; j < 4; j++)
        tile[ty + j * 8][tx] = W[(size_t)(k0 + ty + j * 8) * N + n0 + tx];
    __syncthreads();
#pragma unroll
    for (int j = 0; j < 4; j++)
        Y[(size_t)(rowOff + n0 + ty + j * 8) * K + k0 + tx] =
            __float2half_rn(tile[tx][ty + j * 8]);
}

__global__ void bkv_kernel(const float* __restrict__ bk, const float* __restrict__ bv,
                           float* __restrict__ bkv)
{
    int i = blockIdx.x * blockDim.x + threadIdx.x;
    if (i < DMODEL) { bkv[i] = bk[i]; bkv[DMODEL + i] = bv[i]; }
}

// ---------------- HMMA flash-attention (fused K|V buffer, row stride 2048) -----
#define AQT 128
#define KVW (2 * DMODEL)

__global__ void __launch_bounds__(256, 2) attn_kernel(
    const __half* __restrict__ Qh, const __half* __restrict__ KVh,
    __half* __restrict__ O)
{
    extern __shared__ char smraw[];
    const uint32_t smb = smem_u32(smraw);
    const uint32_t sQ = smb;             // 128 x 128B = 16KB
    const uint32_t sK = smb + 16384;     // 256 x 128B = 32KB
    const uint32_t sV = smb + 49152;     // 256 x 128B = 32KB

    const int bid   = blockIdx.x;
    const int chunk = bid & 31;
    const int h     = (bid >> 5) & 15;
    const int b     = bid >> 9;

    const int tid  = threadIdx.x;
    const int lane = tid & 31;
    const int w    = tid >> 5;

    {
        const __half* qg = Qh + (size_t)(b * TXQ + chunk * AQT) * DMODEL + h * HDIM;
        const __half* kg = KVh + (size_t)(b * TXFK) * KVW + h * HDIM;
        const __half* vg = kg + DMODEL;
#pragma unroll
        for (int i = 0; i < 4; i++) {
            int idx = tid + i * 256;
            int row = idx >> 3, cc = idx & 7;
            uint32_t off = row * 128 + ((cc ^ (row & 7)) << 4);
            cp16(sQ + off, qg + (size_t)row * DMODEL + cc * 8);
        }
#pragma unroll
        for (int i = 0; i < 8; i++) {
            int idx = tid + i * 256;
            int row = idx >> 3, cc = idx & 7;
            uint32_t off = row * 128 + ((cc ^ (row & 7)) << 4);
            cp16(sK + off, kg + (size_t)row * KVW + cc * 8);
            cp16(sV + off, vg + (size_t)row * KVW + cc * 8);
        }
        asm volatile("cp.async.commit_group;" ::: "memory");
        asm volatile("cp.async.wait_group 0;" ::: "memory");
        __syncthreads();
    }

    uint32_t qf[4][4];
#pragma unroll
    for (int s = 0; s < 4; s++) {
        int row = w * 16 + (lane & 15);
        int cc = 2 * s + (lane >> 4);
        ldsm4(qf[s], sQ + row * 128 + ((cc ^ (row & 7)) << 4));
    }

    float oacc[8][4];
#pragma unroll
    for (int j = 0; j < 8; j++)
#pragma unroll
        for (int q = 0; q < 4; q++) oacc[j][q] = 0.0f;
    float m0 = -1e30f, m1 = -1e30f, l0 = 0.0f, l1 = 0.0f;

    for (int c = 0; c < 4; c++) {
        const int kb = c * 64;
        float sacc[8][4];
#pragma unroll
        for (int j = 0; j < 8; j++)
#pragma unroll
            for (int q = 0; q < 4; q++) sacc[j][q] = 0.0f;

#pragma unroll
        for (int s = 0; s < 4; s++) {
#pragma unroll
            for (int njp = 0; njp < 4; njp++) {
                uint32_t kf[4];
                int row = kb + njp * 16 + (lane & 7) + ((lane >> 4) << 3);
                int cc = 2 * s + ((lane >> 3) & 1);
                ldsm4(kf, sK + row * 128 + ((cc ^ (row & 7)) << 4));
                mma16816(sacc[njp * 2],     qf[s], kf[0], kf[1]);
                mma16816(sacc[njp * 2 + 1], qf[s], kf[2], kf[3]);
            }
        }

        float mx0 = -1e30f, mx1 = -1e30f;
#pragma unroll
        for (int j = 0; j < 8; j++) {
            sacc[j][0] *= ATT_SCALE; sacc[j][1] *= ATT_SCALE;
            sacc[j][2] *= ATT_SCALE; sacc[j][3] *= ATT_SCALE;
            mx0 = fmaxf(mx0, fmaxf(sacc[j][0], sacc[j][1]));
            mx1 = fmaxf(mx1, fmaxf(sacc[j][2], sacc[j][3]));
        }
        mx0 = fmaxf(mx0, __shfl_xor_sync(~0u, mx0, 1));
        mx0 = fmaxf(mx0, __shfl_xor_sync(~0u, mx0, 2));
        mx1 = fmaxf(mx1, __shfl_xor_sync(~0u, mx1, 1));
        mx1 = fmaxf(mx1, __shfl_xor_sync(~0u, mx1, 2));
        float m0n = fmaxf(m0, mx0), m1n = fmaxf(m1, mx1);
        float sc0 = fexp(m0 - m0n), sc1 = fexp(m1 - m1n);
        m0 = m0n; m1 = m1n;

        float rs0 = 0.0f, rs1 = 0.0f;
#pragma unroll
        for (int j = 0; j < 8; j++) {
            sacc[j][0] = fexp(sacc[j][0] - m0);
            sacc[j][1] = fexp(sacc[j][1] - m0);
            sacc[j][2] = fexp(sacc[j][2] - m1);
            sacc[j][3] = fexp(sacc[j][3] - m1);
            rs0 += sacc[j][0] + sacc[j][1];
            rs1 += sacc[j][2] + sacc[j][3];
        }
        rs0 += __shfl_xor_sync(~0u, rs0, 1);
        rs0 += __shfl_xor_sync(~0u, rs0, 2);
        rs1 += __shfl_xor_sync(~0u, rs1, 1);
        rs1 += __shfl_xor_sync(~0u, rs1, 2);
        l0 = l0 * sc0 + rs0;
        l1 = l1 * sc1 + rs1;
#pragma unroll
        for (int j = 0; j < 8; j++) {
            oacc[j][0] *= sc0; oacc[j][1] *= sc0;
            oacc[j][2] *= sc1; oacc[j][3] *= sc1;
        }

#pragma unroll
        for (int t2 = 0; t2 < 4; t2++) {
            uint32_t pf[4];
            pf[0] = pack_h2(sacc[2 * t2][0],     sacc[2 * t2][1]);
            pf[1] = pack_h2(sacc[2 * t2][2],     sacc[2 * t2][3]);
            pf[2] = pack_h2(sacc[2 * t2 + 1][0], sacc[2 * t2 + 1][1]);
            pf[3] = pack_h2(sacc[2 * t2 + 1][2], sacc[2 * t2 + 1][3]);
            const int kk = kb + t2 * 16;
#pragma unroll
            for (int ndp = 0; ndp < 4; ndp++) {
                uint32_t vf[4];
                int row = kk + ((lane >> 3) & 1) * 8 + (lane & 7);
                int cc = 2 * ndp + (lane >> 4);
                ldsm4t(vf, sV + row * 128 + ((cc ^ (row & 7)) << 4));
                mma16816(oacc[ndp * 2],     pf, vf[0], vf[1]);
                mma16816(oacc[ndp * 2 + 1], pf, vf[2], vf[3]);
            }
        }
    }

    const float inv0 = 1.0f / l0, inv1 = 1.0f / l1;
    const int g = lane >> 2, t = lane & 3;
    const size_t row0 = (size_t)(b * TXQ + chunk * AQT + w * 16 + g);
#pragma unroll
    for (int j = 0; j < 8; j++) {
        int col = h * HDIM + j * 8 + 2 * t;
        *(uint32_t*)(O + row0 * DMODEL + col) =
            pack_h2(oacc[j][0] * inv0, oacc[j][1] * inv0);
        *(uint32_t*)(O + (row0 + 8) * DMODEL + col) =
            pack_h2(oacc[j][2] * inv1, oacc[j][3] * inv1);
    }
}

// ---------------- LayerNorm -> fp16 --------------------------------------------
__global__ void __launch_bounds__(256) ln_conv_kernel(
    const float* __restrict__ X, const float* __restrict__ gw,
    const float* __restrict__ bw, __half* __restrict__ Y)
{
    const int row = blockIdx.x;
    const int t = threadIdx.x;
    float4 v = ((const float4*)(X + (size_t)row * DMODEL))[t];
    float s1 = v.x + v.y + v.z + v.w;
    float s2 = v.x * v.x + v.y * v.y + v.z * v.z + v.w * v.w;
#pragma unroll
    for (int o = 16; o; o >>= 1) {
        s1 += __shfl_xor_sync(~0u, s1, o);
        s2 += __shfl_xor_sync(~0u, s2, o);
    }
    __shared__ float r1[8], r2[8];
    const int w = t >> 5, lane = t & 31;
    if (lane == 0) { r1[w] = s1; r2[w] = s2; }
    __syncthreads();
    if (w == 0) {
        s1 = (lane < 8) ? r1[lane] : 0.0f;
        s2 = (lane < 8) ? r2[lane] : 0.0f;
#pragma unroll
        for (int o = 4; o; o >>= 1) {
            s1 += __shfl_xor_sync(~0u, s1, o);
            s2 += __shfl_xor_sync(~0u, s2, o);
        }
        if (lane == 0) { r1[0] = s1; r2[0] = s2; }
    }
    __syncthreads();
    const float mean = r1[0] * (1.0f / DMODEL);
    const float var  = r2[0] * (1.0f / DMODEL) - mean * mean;
    const float rstd = rsqrtf(var + 1e-5f);
    float4 g4 = ((const float4*)gw)[t];
    float4 b4 = ((const float4*)bw)[t];
    float vv[4];
    vv[0] = (v.x - mean) * rstd * g4.x + b4.x;
    vv[1] = (v.y - mean) * rstd * g4.y + b4.y;
    vv[2] = (v.z - mean) * rstd * g4.z + b4.z;
    vv[3] = (v.w - mean) * rstd * g4.w + b4.w;

    *(uint2*)(Y + (size_t)row * DMODEL + t * 4) =
        make_uint2(pack_h2(vv[0], vv[1]), pack_h2(vv[2], vv[3]));
}

// ---------------- launch -------------------------------------------------------
extern "C" void kernel_launch(void* const* d_in, const int* in_sizes, int n_in,
                              void* d_out, int out_size)
{
    const float* x    = (const float*)d_in[0];
    const float* xf   = (const float*)d_in[1];
    const float* Wq   = (const float*)d_in[2];
    const float* bq   = (const float*)d_in[3];
    const float* Wk   = (const float*)d_in[4];
    const float* bk   = (const float*)d_in[5];
    const float* Wv   = (const float*)d_in[6];
    const float* bv   = (const float*)d_in[7];
    const float* Wo   = (const float*)d_in[8];
    const float* bo   = (const float*)d_in[9];
    const float* ln_g = (const float*)d_in[10];
    const float* ln_b = (const float*)d_in[11];
    const float* W1   = (const float*)d_in[12];
    const float* b1   = (const float*)d_in[13];
    const float* W2   = (const float*)d_in[14];
    const float* b2   = (const float*)d_in[15];
    float* out = (float*)d_out;

    float *res, *bkv;
    __half *xs, *xfs, *qh, *kvh, *attns, *lns, *hs, *wq, *wkv, *wo, *w1, *w2;
    cudaGetSymbolAddress((void**)&res,   g_res);
    cudaGetSymbolAddress((void**)&bkv,   g_bkv);
    cudaGetSymbolAddress((void**)&xs,    g_xs);
    cudaGetSymbolAddress((void**)&xfs,   g_xfs);
    cudaGetSymbolAddress((void**)&qh,    g_qh);
    cudaGetSymbolAddress((void**)&kvh,   g_kvh);
    cudaGetSymbolAddress((void**)&attns, g_attns);
    cudaGetSymbolAddress((void**)&lns,   g_lns);
    cudaGetSymbolAddress((void**)&hs,    g_hs);
    cudaGetSymbolAddress((void**)&wq,    g_wq);
    cudaGetSymbolAddress((void**)&wkv,   g_wkv);
    cudaGetSymbolAddress((void**)&wo,    g_wo);
    cudaGetSymbolAddress((void**)&w1,    g_w1);
    cudaGetSymbolAddress((void**)&w2,    g_w2);

    const int GEMM_SMEM = NSTAGE * STAGE_BYTES;   // 96KB
    cudaFuncSetAttribute(mma_gemm<0>, cudaFuncAttributeMaxDynamicSharedMemorySize, GEMM_SMEM);
    cudaFuncSetAttribute(mma_gemm<2>, cudaFuncAttributeMaxDynamicSharedMemorySize, GEMM_SMEM);
    cudaFuncSetAttribute(mma_gemm<3>, cudaFuncAttributeMaxDynamicSharedMemorySize, GEMM_SMEM);
    cudaFuncSetAttribute(mma_gemm<4>, cudaFuncAttributeMaxDynamicSharedMemorySize, GEMM_SMEM);
    const int ATTN_SMEM = 81920;                  // 16KB Q + 32KB K + 32KB V
    cudaFuncSetAttribute(attn_kernel, cudaFuncAttributeMaxDynamicSharedMemorySize, ATTN_SMEM);

    dim3 blk(256);
    dim3 tblk(32, 8);
    auto cdiv = [](size_t a, size_t b) { return (unsigned)((a + b - 1) / b); };

    // weight transpose+convert (tiled, coalesced)
    wtrans_kernel<<<dim3(DMODEL / 32, DMODEL / 32), tblk>>>(Wq, wq, DMODEL, DMODEL, 0);
    wtrans_kernel<<<dim3(DMODEL / 32, DTEXT  / 32), tblk>>>(Wk, wkv, DTEXT, DMODEL, 0);
    wtrans_kernel<<<dim3(DMODEL / 32, DTEXT  / 32), tblk>>>(Wv, wkv, DTEXT, DMODEL, DMODEL);
    wtrans_kernel<<<dim3(DMODEL / 32, DMODEL / 32), tblk>>>(Wo, wo, DMODEL, DMODEL, 0);
    wtrans_kernel<<<dim3(DFF    / 32, DMODEL / 32), tblk>>>(W1, w1, DMODEL, DFF, 0);
    wtrans_kernel<<<dim3(DMODEL / 32, DFF    / 32), tblk>>>(W2, w2, DFF, DMODEL, 0);
    bkv_kernel<<<cdiv(DMODEL, 256), blk>>>(bk, bv, bkv);
    // activation converts
    aconv_kernel<<<cdiv((size_t)MQ  * DMODEL / 4, 256), blk>>>(x,  xs,  (size_t)MQ  * DMODEL);
    aconv_kernel<<<cdiv((size_t)MKV * DTEXT  / 4, 256), blk>>>(xf, xfs, (size_t)MKV * DTEXT);

    // Q projection -> fp16 ; fused K|V projection -> fp16 (N=2048)
    mma_gemm<4><<<dim3(DMODEL / 128, MQ / 128), blk, GEMM_SMEM>>>(
        DMODEL, DMODEL, xs, wq, bq, nullptr, nullptr, nullptr, qh, DMODEL);
    mma_gemm<4><<<dim3(2 * DMODEL / 128, MKV / 128), blk, GEMM_SMEM>>>(
        2 * DMODEL, DTEXT, xfs, wkv, bkv, nullptr, nullptr, nullptr, kvh, 2 * DMODEL);

    // HMMA flash-attention -> fp16
    attn_kernel<<<BDIM * NHEADS * (TXQ / AQT), blk, ATTN_SMEM>>>(qh, kvh, attns);

    // out = attn@Wo + bo (residual base, fp32)
    mma_gemm<0><<<dim3(DMODEL / 128, MQ / 128), blk, GEMM_SMEM>>>(
        DMODEL, DMODEL, attns, wo, bo, nullptr, nullptr, res, nullptr, 0);

    // LayerNorm -> fp16
    ln_conv_kernel<<<MQ, blk>>>(res, ln_g, ln_b, lns);

    // h = GELU(ln@W1 + b1) -> fp16
    mma_gemm<2><<<dim3(DFF / 128, MQ / 128), blk, GEMM_SMEM>>>(
        DFF, DMODEL, lns, w1, b1, nullptr, nullptr, nullptr, hs, DFF);

    // final = h@W2 + b2 + res + x
    mma_gemm<3><<<dim3(DMODEL / 128, MQ / 128), blk, GEMM_SMEM>>>(
        DMODEL, DFF, hs, w2, b2, res, x, out, nullptr, 0);
}

// round 14
// speedup vs baseline: 3.7980x; 1.0233x over previous
#include <cuda_runtime.h>
#include <cuda_fp16.h>
#include <math.h>
#include <stdint.h>

#define BDIM   4
#define TXQ    4096
#define TXFK   256
#define DMODEL 1024
#define DTEXT  768
#define NHEADS 16
#define HDIM   64
#define MQ     (BDIM*TXQ)     // 16384
#define MKV    (BDIM*TXFK)    // 1024
#define DFF    4096
#define ATT_SCALE 0.125f
#define SCALE_LOG2E 0.1803368801111906f   // ATT_SCALE * log2(e)

// ---------------- scratch (device globals) -----------------------------------
__device__ float g_res [(size_t)MQ * DMODEL];
__device__ float g_bkv [2 * DMODEL];

// fp16 buffers
__device__ __half g_xs   [(size_t)MQ  * DMODEL];
__device__ __half g_xfs  [(size_t)MKV * DTEXT];
__device__ __half g_qh   [(size_t)MQ  * DMODEL];
__device__ __half g_kvh  [(size_t)MKV * 2 * DMODEL];   // [K | V] fused, row 2048
__device__ __half g_attns[(size_t)MQ  * DMODEL];
__device__ __half g_lns  [(size_t)MQ  * DMODEL];
__device__ __half g_hs   [(size_t)MQ  * DFF];
__device__ __half g_wq   [(size_t)DMODEL * DMODEL];
__device__ __half g_wkv  [(size_t)2 * DMODEL * DTEXT];
__device__ __half g_wo   [(size_t)DMODEL * DMODEL];
__device__ __half g_w1   [(size_t)DFF    * DMODEL];
__device__ __half g_w2   [(size_t)DMODEL * DFF];

__device__ __forceinline__ float gelu_exact(float v) {
    return 0.5f * v * (1.0f + erff(v * 0.7071067811865476f));
}

// ---------------- PTX helpers (target-portable, sm_80+) -----------------------
__device__ __forceinline__ uint32_t smem_u32(const void* p) {
    uint32_t a;
    asm("{ .reg .u64 t; cvta.to.shared.u64 t, %1; cvt.u32.u64 %0, t; }"
        : "=r"(a) : "l"(p));
    return a;
}
__device__ __forceinline__ void cp16(uint32_t s, const void* g) {
    asm volatile("cp.async.cg.shared.global [%0], [%1], 16;" :: "r"(s), "l"(g));
}
__device__ __forceinline__ void ldsm4(uint32_t* r, uint32_t a) {
    asm volatile("ldmatrix.sync.aligned.m8n8.x4.shared.b16 {%0,%1,%2,%3}, [%4];"
        : "=r"(r[0]), "=r"(r[1]), "=r"(r[2]), "=r"(r[3]) : "r"(a));
}
__device__ __forceinline__ void ldsm4t(uint32_t* r, uint32_t a) {
    asm volatile("ldmatrix.sync.aligned.m8n8.x4.trans.shared.b16 {%0,%1,%2,%3}, [%4];"
        : "=r"(r[0]), "=r"(r[1]), "=r"(r[2]), "=r"(r[3]) : "r"(a));
}
__device__ __forceinline__ void mma16816(float* c, const uint32_t* a,
                                         uint32_t b0, uint32_t b1) {
    asm volatile(
        "mma.sync.aligned.m16n8k16.row.col.f32.f16.f16.f32 "
        "{%0,%1,%2,%3}, {%4,%5,%6,%7}, {%8,%9}, {%0,%1,%2,%3};"
        : "+f"(c[0]), "+f"(c[1]), "+f"(c[2]), "+f"(c[3])
        : "r"(a[0]), "r"(a[1]), "r"(a[2]), "r"(a[3]), "r"(b0), "r"(b1));
}
__device__ __forceinline__ uint32_t pack_h2(float a, float b) {
    __half2 t = __floats2half2_rn(a, b);
    uint32_t u; memcpy(&u, &t, 4); return u;
}
// exp2 on FMA pipe. y <= 0 expected; rel err ~2e-6.
__device__ __forceinline__ float fexp2(float y) {
    y = fmaxf(y, -80.0f);
    float r = rintf(y);
    float f = y - r;
    float p =          1.3333558e-3f;
    p = fmaf(p, f,     9.6181291e-3f);
    p = fmaf(p, f,     5.5504109e-2f);
    p = fmaf(p, f,     2.4022651e-1f);
    p = fmaf(p, f,     6.9314718e-1f);
    p = fmaf(p, f,     1.0f);
    return __int_as_float(__float_as_int(p) + (((int)r) << 23));
}

// ---------------- pure fp16 HMMA GEMM ------------------------------------------
#define STAGE_BYTES 32768
#define NSTAGE 3
#define RASTER_G 16

template<int MODE>
__global__ void __launch_bounds__(256, 2) mma_gemm(
    int Nn, int Kk,
    const __half* __restrict__ A, const __half* __restrict__ Bw,
    const float* __restrict__ bias,
    const float* __restrict__ res1, const float* __restrict__ res2,
    float* __restrict__ Cf, __half* __restrict__ Cb, int KOUT)
{
    extern __shared__ char smraw[];
    const uint32_t smb = smem_u32(smraw);

    const int tid = threadIdx.x;
    const int numX = gridDim.x, numY = gridDim.y;
    const int bid = blockIdx.y * numX + blockIdx.x;
    const int strip = RASTER_G * numX;
    const int sIdx = bid / strip;
    const int rIdx = bid % strip;
    const int gRows = (numY - sIdx * RASTER_G) < RASTER_G ? (numY - sIdx * RASTER_G)
                                                          : RASTER_G;
    const int by = sIdx * RASTER_G + (rIdx % gRows);
    const int bx = rIdx / gRows;

    const int w = tid >> 5, lane = tid & 31;
    const int m0w = (w & 3) * 32, n0w = (w >> 2) * 64;

    const __half* Abase = A  + (size_t)(by * 128) * Kk;
    const __half* Bbase = Bw + (size_t)(bx * 128) * Kk;
    const int nch = Kk >> 6;

    auto load_stage = [&](int c, int s) {
        const uint32_t sa = smb + s * STAGE_BYTES;
        const uint32_t sb = sa + 16384;
        const int k0 = c * 64;
#pragma unroll
        for (int i = 0; i < 4; i++) {
            int idx = tid + i * 256;
            int row = idx >> 3, cc = idx & 7;
            uint32_t off = row * 128 + ((cc ^ (row & 7)) << 4);
            cp16(sa + off, Abase + (size_t)row * Kk + k0 + cc * 8);
            cp16(sb + off, Bbase + (size_t)row * Kk + k0 + cc * 8);
        }
        asm volatile("cp.async.commit_group;" ::: "memory");
    };

    float acc[2][8][4];
#pragma unroll
    for (int i = 0; i < 2; i++)
#pragma unroll
        for (int j = 0; j < 8; j++)
#pragma unroll
            for (int q = 0; q < 4; q++) acc[i][j][q] = 0.0f;

    const int a_row = m0w + (lane & 15);
    const int a_ccb = lane >> 4;
    const int b_row = n0w + (lane & 7) + ((lane >> 4) << 3);
    const int b_ccb = (lane >> 3) & 1;

    load_stage(0, 0);
    if (nch > 1) load_stage(1, 1);

    for (int c = 0; c < nch; c++) {
        const int s = c % NSTAGE;
        if (c + 1 < nch) asm volatile("cp.async.wait_group 1;" ::: "memory");
        else             asm volatile("cp.async.wait_group 0;" ::: "memory");
        __syncthreads();
        if (c + 2 < nch) load_stage(c + 2, (c + 2) % NSTAGE);

        const uint32_t sa = smb + s * STAGE_BYTES;
        const uint32_t sb = sa + 16384;
#pragma unroll
        for (int kk = 0; kk < 4; kk++) {
            uint32_t af[2][4];
#pragma unroll
            for (int mi = 0; mi < 2; mi++) {
                int row = a_row + mi * 16;
                int cc = kk * 2 + a_ccb;
                ldsm4(af[mi], sa + row * 128 + ((cc ^ (row & 7)) << 4));
            }
#pragma unroll
            for (int nj = 0; nj < 4; nj++) {
                uint32_t bf[4];
                int row = b_row + nj * 16;
                int cc = kk * 2 + b_ccb;
                ldsm4(bf, sb + row * 128 + ((cc ^ (row & 7)) << 4));
#pragma unroll
                for (int mi = 0; mi < 2; mi++) {
                    mma16816(acc[mi][nj * 2],     af[mi], bf[0], bf[1]);
                    mma16816(acc[mi][nj * 2 + 1], af[mi], bf[2], bf[3]);
                }
            }
        }
    }

    const int g = lane >> 2, t = lane & 3;
#pragma unroll
    for (int mi = 0; mi < 2; mi++) {
#pragma unroll
        for (int ni = 0; ni < 8; ni++) {
            const int col = bx * 128 + n0w + ni * 8 + 2 * t;
            const float b0 = __ldg(bias + col);
            const float b1 = __ldg(bias + col + 1);
            const int row0 = by * 128 + m0w + mi * 16 + g;
#pragma unroll
            for (int h = 0; h < 2; h++) {
                const int row = row0 + h * 8;
                float v0 = acc[mi][ni][2 * h]     + b0;
                float v1 = acc[mi][ni][2 * h + 1] + b1;
                if (MODE == 2) {
                    v0 = gelu_exact(v0); v1 = gelu_exact(v1);
                    *(uint32_t*)(Cb + (size_t)row * KOUT + col) = pack_h2(v0, v1);
                } else if (MODE == 4) {
                    *(uint32_t*)(Cb + (size_t)row * KOUT + col) = pack_h2(v0, v1);
                } else {
                    const size_t base = (size_t)row * Nn + col;
                    if (MODE == 3) {
                        v0 += res1[base]     + res2[base];
                        v1 += res1[base + 1] + res2[base + 1];
                    }
                    *(float2*)(Cf + base) = make_float2(v0, v1);
                }
            }
        }
    }
}

// ---------------- merged prep kernel -------------------------------------------
// All weight transposes + activation converts + bias concat in ONE launch.
// 256 threads/block. Transpose tiles are 32x32 (tx=tid&31, ty=tid>>5, 8 rows).
#define TB_WQ   1024                       // (1024/32)*(1024/32)
#define TB_WK   768                        // (1024/32)*(768/32)
#define TB_WV   768
#define TB_WO   1024
#define TB_W1   4096                       // (4096/32)*(1024/32)
#define TB_W2   4096                       // (1024/32)*(4096/32)
#define CB_X    8192                       // 16777216 / 2048
#define CB_XF   384                        // 786432 / 2048
#define PREP_BLOCKS (TB_WQ+TB_WK+TB_WV+TB_WO+TB_W1+TB_W2+CB_X+CB_XF+1)

__device__ __forceinline__ void trans_tile(
    const float* __restrict__ W, __half* __restrict__ Y,
    int K, int N, int rowOff, int tileIdx, int tid)
{
    __shared__ float tile[32][33];
    const int nt = N >> 5;
    const int bx = tileIdx % nt, by = tileIdx / nt;
    const int n0 = bx * 32, k0 = by * 32;
    const int tx = tid & 31, ty = tid >> 5;
#pragma unroll
    for (int j = 0; j < 4; j++)
        tile[ty + j * 8][tx] = W[(size_t)(k0 + ty + j * 8) * N + n0 + tx];
    __syncthreads();
#pragma unroll
    for (int j = 0; j < 4; j++)
        Y[(size_t)(rowOff + n0 + ty + j * 8) * K + k0 + tx] =
            __float2half_rn(tile[tx][ty + j * 8]);
}

__device__ __forceinline__ void conv_seg(
    const float* __restrict__ X, __half* __restrict__ Y, int segIdx, int tid)
{
    size_t base = (size_t)segIdx * 2048 + tid * 8;
    float4 a = *(const float4*)(X + base);
    float4 b = *(const float4*)(X + base + 4);
    *(uint4*)(Y + base) = make_uint4(pack_h2(a.x, a.y), pack_h2(a.z, a.w),
                                    pack_h2(b.x, b.y), pack_h2(b.z, b.w));
}

__global__ void __launch_bounds__(256) prep_kernel(
    const float* __restrict__ Wq, const float* __restrict__ Wk,
    const float* __restrict__ Wv, const float* __restrict__ Wo,
    const float* __restrict__ W1, const float* __restrict__ W2,
    const float* __restrict__ x,  const float* __restrict__ xf,
    const float* __restrict__ bk, const float* __restrict__ bv,
    __half* __restrict__ wq, __half* __restrict__ wkv, __half* __restrict__ wo,
    __half* __restrict__ w1, __half* __restrict__ w2,
    __half* __restrict__ xs, __half* __restrict__ xfs, float* __restrict__ bkv)
{
    int b = blockIdx.x;
    const int tid = threadIdx.x;
    if (b < TB_WQ)  { trans_tile(Wq, wq,  DMODEL, DMODEL, 0,      b, tid); return; }
    b -= TB_WQ;
    if (b < TB_WK)  { trans_tile(Wk, wkv, DTEXT,  DMODEL, 0,      b, tid); return; }
    b -= TB_WK;
    if (b < TB_WV)  { trans_tile(Wv, wkv, DTEXT,  DMODEL, DMODEL, b, tid); return; }
    b -= TB_WV;
    if (b < TB_WO)  { trans_tile(Wo, wo,  DMODEL, DMODEL, 0,      b, tid); return; }
    b -= TB_WO;
    if (b < TB_W1)  { trans_tile(W1, w1,  DMODEL, DFF,    0,      b, tid); return; }
    b -= TB_W1;
    if (b < TB_W2)  { trans_tile(W2, w2,  DFF,    DMODEL, 0,      b, tid); return; }
    b -= TB_W2;
    if (b < CB_X)   { conv_seg(x,  xs,  b, tid); return; }
    b -= CB_X;
    if (b < CB_XF)  { conv_seg(xf, xfs, b, tid); return; }
    // bias concat (1 block)
    for (int i = tid; i < DMODEL; i += 256) {
        bkv[i] = bk[i]; bkv[DMODEL + i] = bv[i];
    }
}

// ---------------- HMMA flash-attention (exp2-domain softmax, joint max) --------
#define AQT 128
#define KVW (2 * DMODEL)

__global__ void __launch_bounds__(256, 2) attn_kernel(
    const __half* __restrict__ Qh, const __half* __restrict__ KVh,
    __half* __restrict__ O)
{
    extern __shared__ char smraw[];
    const uint32_t smb = smem_u32(smraw);
    const uint32_t sQ = smb;
    const uint32_t sK = smb + 16384;
    const uint32_t sV = smb + 49152;

    const int bid   = blockIdx.x;
    const int chunk = bid & 31;
    const int h     = (bid >> 5) & 15;
    const int b     = bid >> 9;

    const int tid  = threadIdx.x;
    const int lane = tid & 31;
    const int w    = tid >> 5;

    {
        const __half* qg = Qh + (size_t)(b * TXQ + chunk * AQT) * DMODEL + h * HDIM;
        const __half* kg = KVh + (size_t)(b * TXFK) * KVW + h * HDIM;
        const __half* vg = kg + DMODEL;
#pragma unroll
        for (int i = 0; i < 4; i++) {
            int idx = tid + i * 256;
            int row = idx >> 3, cc = idx & 7;
            uint32_t off = row * 128 + ((cc ^ (row & 7)) << 4);
            cp16(sQ + off, qg + (size_t)row * DMODEL + cc * 8);
        }
#pragma unroll
        for (int i = 0; i < 8; i++) {
            int idx = tid + i * 256;
            int row = idx >> 3, cc = idx & 7;
            uint32_t off = row * 128 + ((cc ^ (row & 7)) << 4);
            cp16(sK + off, kg + (size_t)row * KVW + cc * 8);
            cp16(sV + off, vg + (size_t)row * KVW + cc * 8);
        }
        asm volatile("cp.async.commit_group;" ::: "memory");
        asm volatile("cp.async.wait_group 0;" ::: "memory");
        __syncthreads();
    }

    uint32_t qf[4][4];
#pragma unroll
    for (int s = 0; s < 4; s++) {
        int row = w * 16 + (lane & 15);
        int cc = 2 * s + (lane >> 4);
        ldsm4(qf[s], sQ + row * 128 + ((cc ^ (row & 7)) << 4));
    }

    float oacc[8][4];
#pragma unroll
    for (int j = 0; j < 8; j++)
#pragma unroll
        for (int q = 0; q < 4; q++) oacc[j][q] = 0.0f;
    float m = -1e30f, l0 = 0.0f, l1 = 0.0f;   // joint running max (exp2 domain)

    for (int c = 0; c < 4; c++) {
        const int kb = c * 64;
        float sacc[8][4];
#pragma unroll
        for (int j = 0; j < 8; j++)
#pragma unroll
            for (int q = 0; q < 4; q++) sacc[j][q] = 0.0f;

#pragma unroll
        for (int s = 0; s < 4; s++) {
#pragma unroll
            for (int njp = 0; njp < 4; njp++) {
                uint32_t kf[4];
                int row = kb + njp * 16 + (lane & 7) + ((lane >> 4) << 3);
                int cc = 2 * s + ((lane >> 3) & 1);
                ldsm4(kf, sK + row * 128 + ((cc ^ (row & 7)) << 4));
                mma16816(sacc[njp * 2],     qf[s], kf[0], kf[1]);
                mma16816(sacc[njp * 2 + 1], qf[s], kf[2], kf[3]);
            }
        }

        // joint max over raw scores (exp2 domain after scaling by SCALE_LOG2E)
        float mx = -1e30f;
#pragma unroll
        for (int j = 0; j < 8; j++) {
            mx = fmaxf(mx, fmaxf(fmaxf(sacc[j][0], sacc[j][1]),
                                 fmaxf(sacc[j][2], sacc[j][3])));
        }
        mx = fmaxf(mx, __shfl_xor_sync(~0u, mx, 1));
        mx = fmaxf(mx, __shfl_xor_sync(~0u, mx, 2));
        float mn = fmaxf(m, mx * SCALE_LOG2E);
        float sc = fexp2(m - mn);
        m = mn;

        float rs0 = 0.0f, rs1 = 0.0f;
#pragma unroll
        for (int j = 0; j < 8; j++) {
            sacc[j][0] = fexp2(fmaf(sacc[j][0], SCALE_LOG2E, -m));
            sacc[j][1] = fexp2(fmaf(sacc[j][1], SCALE_LOG2E, -m));
            sacc[j][2] = fexp2(fmaf(sacc[j][2], SCALE_LOG2E, -m));
            sacc[j][3] = fexp2(fmaf(sacc[j][3], SCALE_LOG2E, -m));
            rs0 += sacc[j][0] + sacc[j][1];
            rs1 += sacc[j][2] + sacc[j][3];
        }
        rs0 += __shfl_xor_sync(~0u, rs0, 1);
        rs0 += __shfl_xor_sync(~0u, rs0, 2);
        rs1 += __shfl_xor_sync(~0u, rs1, 1);
        rs1 += __shfl_xor_sync(~0u, rs1, 2);
        l0 = l0 * sc + rs0;
        l1 = l1 * sc + rs1;
#pragma unroll
        for (int j = 0; j < 8; j++) {
            oacc[j][0] *= sc; oacc[j][1] *= sc;
            oacc[j][2] *= sc; oacc[j][3] *= sc;
        }

#pragma unroll
        for (int t2 = 0; t2 < 4; t2++) {
            uint32_t pf[4];
            pf[0] = pack_h2(sacc[2 * t2][0],     sacc[2 * t2][1]);
            pf[1] = pack_h2(sacc[2 * t2][2],     sacc[2 * t2][3]);
            pf[2] = pack_h2(sacc[2 * t2 + 1][0], sacc[2 * t2 + 1][1]);
            pf[3] = pack_h2(sacc[2 * t2 + 1][2], sacc[2 * t2 + 1][3]);
            const int kk = kb + t2 * 16;
#pragma unroll
            for (int ndp = 0; ndp < 4; ndp++) {
                uint32_t vf[4];
                int row = kk + ((lane >> 3) & 1) * 8 + (lane & 7);
                int cc = 2 * ndp + (lane >> 4);
                ldsm4t(vf, sV + row * 128 + ((cc ^ (row & 7)) << 4));
                mma16816(oacc[ndp * 2],     pf, vf[0], vf[1]);
                mma16816(oacc[ndp * 2 + 1], pf, vf[2], vf[3]);
            }
        }
    }

    const float inv0 = 1.0f / l0, inv1 = 1.0f / l1;
    const int g = lane >> 2, t = lane & 3;
    const size_t row0 = (size_t)(b * TXQ + chunk * AQT + w * 16 + g);
#pragma unroll
    for (int j = 0; j < 8; j++) {
        int col = h * HDIM + j * 8 + 2 * t;
        *(uint32_t*)(O + row0 * DMODEL + col) =
            pack_h2(oacc[j][0] * inv0, oacc[j][1] * inv0);
        *(uint32_t*)(O + (row0 + 8) * DMODEL + col) =
            pack_h2(oacc[j][2] * inv1, oacc[j][3] * inv1);
    }
}

// ---------------- LayerNorm -> fp16 --------------------------------------------
__global__ void __launch_bounds__(256) ln_conv_kernel(
    const float* __restrict__ X, const float* __restrict__ gw,
    const float* __restrict__ bw, __half* __restrict__ Y)
{
    const int row = blockIdx.x;
    const int t = threadIdx.x;
    float4 v = ((const float4*)(X + (size_t)row * DMODEL))[t];
    float s1 = v.x + v.y + v.z + v.w;
    float s2 = v.x * v.x + v.y * v.y + v.z * v.z + v.w * v.w;
#pragma unroll
    for (int o = 16; o; o >>= 1) {
        s1 += __shfl_xor_sync(~0u, s1, o);
        s2 += __shfl_xor_sync(~0u, s2, o);
    }
    __shared__ float r1[8], r2[8];
    const int w = t >> 5, lane = t & 31;
    if (lane == 0) { r1[w] = s1; r2[w] = s2; }
    __syncthreads();
    if (w == 0) {
        s1 = (lane < 8) ? r1[lane] : 0.0f;
        s2 = (lane < 8) ? r2[lane] : 0.0f;
#pragma unroll
        for (int o = 4; o; o >>= 1) {
            s1 += __shfl_xor_sync(~0u, s1, o);
            s2 += __shfl_xor_sync(~0u, s2, o);
        }
        if (lane == 0) { r1[0] = s1; r2[0] = s2; }
    }
    __syncthreads();
    const float mean = r1[0] * (1.0f / DMODEL);
    const float var  = r2[0] * (1.0f / DMODEL) - mean * mean;
    const float rstd = rsqrtf(var + 1e-5f);
    float4 g4 = ((const float4*)gw)[t];
    float4 b4 = ((const float4*)bw)[t];
    float vv[4];
    vv[0] = (v.x - mean) * rstd * g4.x + b4.x;
    vv[1] = (v.y - mean) * rstd * g4.y + b4.y;
    vv[2] = (v.z - mean) * rstd * g4.z + b4.z;
    vv[3] = (v.w - mean) * rstd * g4.w + b4.w;

    *(uint2*)(Y + (size_t)row * DMODEL + t * 4) =
        make_uint2(pack_h2(vv[0], vv[1]), pack_h2(vv[2], vv[3]));
}

// ---------------- launch -------------------------------------------------------
extern "C" void kernel_launch(void* const* d_in, const int* in_sizes, int n_in,
                              void* d_out, int out_size)
{
    const float* x    = (const float*)d_in[0];
    const float* xf   = (const float*)d_in[1];
    const float* Wq   = (const float*)d_in[2];
    const float* bq   = (const float*)d_in[3];
    const float* Wk   = (const float*)d_in[4];
    const float* bk   = (const float*)d_in[5];
    const float* Wv   = (const float*)d_in[6];
    const float* bv   = (const float*)d_in[7];
    const float* Wo   = (const float*)d_in[8];
    const float* bo   = (const float*)d_in[9];
    const float* ln_g = (const float*)d_in[10];
    const float* ln_b = (const float*)d_in[11];
    const float* W1   = (const float*)d_in[12];
    const float* b1   = (const float*)d_in[13];
    const float* W2   = (const float*)d_in[14];
    const float* b2   = (const float*)d_in[15];
    float* out = (float*)d_out;

    float *res, *bkv;
    __half *xs, *xfs, *qh, *kvh, *attns, *lns, *hs, *wq, *wkv, *wo, *w1, *w2;
    cudaGetSymbolAddress((void**)&res,   g_res);
    cudaGetSymbolAddress((void**)&bkv,   g_bkv);
    cudaGetSymbolAddress((void**)&xs,    g_xs);
    cudaGetSymbolAddress((void**)&xfs,   g_xfs);
    cudaGetSymbolAddress((void**)&qh,    g_qh);
    cudaGetSymbolAddress((void**)&kvh,   g_kvh);
    cudaGetSymbolAddress((void**)&attns, g_attns);
    cudaGetSymbolAddress((void**)&lns,   g_lns);
    cudaGetSymbolAddress((void**)&hs,    g_hs);
    cudaGetSymbolAddress((void**)&wq,    g_wq);
    cudaGetSymbolAddress((void**)&wkv,   g_wkv);
    cudaGetSymbolAddress((void**)&wo,    g_wo);
    cudaGetSymbolAddress((void**)&w1,    g_w1);
    cudaGetSymbolAddress((void**)&w2,    g_w2);

    const int GEMM_SMEM = NSTAGE * STAGE_BYTES;   // 96KB
    cudaFuncSetAttribute(mma_gemm<0>, cudaFuncAttributeMaxDynamicSharedMemorySize, GEMM_SMEM);
    cudaFuncSetAttribute(mma_gemm<2>, cudaFuncAttributeMaxDynamicSharedMemorySize, GEMM_SMEM);
    cudaFuncSetAttribute(mma_gemm<3>, cudaFuncAttributeMaxDynamicSharedMemorySize, GEMM_SMEM);
    cudaFuncSetAttribute(mma_gemm<4>, cudaFuncAttributeMaxDynamicSharedMemorySize, GEMM_SMEM);
    const int ATTN_SMEM = 81920;
    cudaFuncSetAttribute(attn_kernel, cudaFuncAttributeMaxDynamicSharedMemorySize, ATTN_SMEM);

    dim3 blk(256);

    // ONE merged prep launch: all transposes + converts + bias concat
    prep_kernel<<<PREP_BLOCKS, blk>>>(Wq, Wk, Wv, Wo, W1, W2, x, xf, bk, bv,
                                      wq, wkv, wo, w1, w2, xs, xfs, bkv);

    // Q projection -> fp16 ; fused K|V projection -> fp16 (N=2048)
    mma_gemm<4><<<dim3(DMODEL / 128, MQ / 128), blk, GEMM_SMEM>>>(
        DMODEL, DMODEL, xs, wq, bq, nullptr, nullptr, nullptr, qh, DMODEL);
    mma_gemm<4><<<dim3(2 * DMODEL / 128, MKV / 128), blk, GEMM_SMEM>>>(
        2 * DMODEL, DTEXT, xfs, wkv, bkv, nullptr, nullptr, nullptr, kvh, 2 * DMODEL);

    // HMMA flash-attention -> fp16
    attn_kernel<<<BDIM * NHEADS * (TXQ / AQT), blk, ATTN_SMEM>>>(qh, kvh, attns);

    // out = attn@Wo + bo (residual base, fp32)
    mma_gemm<0><<<dim3(DMODEL / 128, MQ / 128), blk, GEMM_SMEM>>>(
        DMODEL, DMODEL, attns, wo, bo, nullptr, nullptr, res, nullptr, 0);

    // LayerNorm -> fp16
    ln_conv_kernel<<<MQ, blk>>>(res, ln_g, ln_b, lns);

    // h = GELU(ln@W1 + b1) -> fp16
    mma_gemm<2><<<dim3(DFF / 128, MQ / 128), blk, GEMM_SMEM>>>(
        DFF, DMODEL, lns, w1, b1, nullptr, nullptr, nullptr, hs, DFF);

    // final = h@W2 + b2 + res + x
    mma_gemm<3><<<dim3(DMODEL / 128, MQ / 128), blk, GEMM_SMEM>>>(
        DMODEL, DFF, hs, w2, b2, res, x, out, nullptr, 0);
}